// round 1
// baseline (speedup 1.0000x reference)
#include <cuda_runtime.h>
#include <math.h>

// Problem constants
#define CB   2
#define CS   2048
#define CHID 2048
#define CNH  16
#define CHD  128
#define CQLR 1536
#define CKVLR 512
#define CBS  (CB*CS)          // 4096
#define CCAT (CKVLR+CHD)      // 640
#define CQHD (2*CHD)          // 256

// ---------------- device scratch (no cudaMalloc allowed) ----------------
static __device__ __align__(256) float g_qa[CBS*CQLR];                        // 25 MB
static __device__ __align__(256) float g_q[(size_t)CBS*CNH*CQHD];             // 64 MB  [b,s,h,256]
static __device__ __align__(256) float g_ckv[(size_t)CBS*CCAT];               // 10 MB  [b,s,640] (k_pe rope'd in place)
static __device__ __align__(256) float g_qcat[(size_t)CB*CNH*CS*CCAT];        // 160 MB [b,h,s,640]
static __device__ __align__(256) float g_scores[(size_t)CB*CNH*CS*CS];        // 512 MB
static __device__ __align__(256) float g_outlat[(size_t)CB*CNH*CS*CKVLR];     // 128 MB
static __device__ __align__(256) float g_outhead[(size_t)CBS*CNH*CHD];        // 32 MB  [b,s,h*128]
static __device__ __align__(256) float g_qab[CNH*CKVLR*CHD];                  // 4 MB   [h,c,d]
static __device__ __align__(256) float g_oab[CNH*CKVLR*CHD];                  // 4 MB

// ---------------- generic tiled GEMM ----------------
// C[m,n] = alpha * sum_k A[m,k]*B(n,k)  (+bias[n]) (+D[m,n])
// B_T=true : B is [N,K] row-major (NT).  B_T=false : B is [K,N] row-major (NN).
// batch z: decomposed as zo=z/zInner, zi=z%zInner; each operand offset = zo*O + zi*I.
template<bool B_T>
__global__ __launch_bounds__(256) void gemm_kernel(
    const float* __restrict__ A, int lda,
    const float* __restrict__ B, int ldb,
    float* __restrict__ C, int ldc,
    const float* __restrict__ D, int ldd,
    const float* __restrict__ bias,
    float alpha, int K, int zInner,
    long long aO, long long aI, long long bO, long long bI,
    long long cO, long long cI, long long dO, long long dI)
{
    const int BK = 8;
    __shared__ float As[BK][128];
    __shared__ float Bs[BK][128];

    int z  = blockIdx.z;
    int zo = z / zInner, zi = z - zo * zInner;
    A += zo*aO + zi*aI;
    B += zo*bO + zi*bI;
    C += zo*cO + zi*cI;
    if (D) D += zo*dO + zi*dI;

    int bm = blockIdx.y * 128;
    int bn = blockIdx.x * 128;
    int tid = threadIdx.x;
    int tx = tid & 15, ty = tid >> 4;

    float acc[8][8];
#pragma unroll
    for (int i = 0; i < 8; i++)
#pragma unroll
        for (int j = 0; j < 8; j++) acc[i][j] = 0.f;

    int lr = tid >> 1;          // 0..127 (row within tile)
    int lk = (tid & 1) * 4;     // 0 or 4 (k quad)
    int nk = tid >> 5;          // 0..7  (k row, NN B load)
    int nr = (tid & 31) * 4;    // 0..124 (n quad, NN B load)

    for (int k0 = 0; k0 < K; k0 += BK) {
        float4 va = *reinterpret_cast<const float4*>(&A[(size_t)(bm + lr) * lda + k0 + lk]);
        As[lk+0][lr] = va.x; As[lk+1][lr] = va.y; As[lk+2][lr] = va.z; As[lk+3][lr] = va.w;
        if (B_T) {
            float4 vb = *reinterpret_cast<const float4*>(&B[(size_t)(bn + lr) * ldb + k0 + lk]);
            Bs[lk+0][lr] = vb.x; Bs[lk+1][lr] = vb.y; Bs[lk+2][lr] = vb.z; Bs[lk+3][lr] = vb.w;
        } else {
            float4 vb = *reinterpret_cast<const float4*>(&B[(size_t)(k0 + nk) * ldb + bn + nr]);
            *reinterpret_cast<float4*>(&Bs[nk][nr]) = vb;
        }
        __syncthreads();
#pragma unroll
        for (int k = 0; k < BK; k++) {
            float a[8], b[8];
            *reinterpret_cast<float4*>(a)   = *reinterpret_cast<const float4*>(&As[k][ty*8]);
            *reinterpret_cast<float4*>(a+4) = *reinterpret_cast<const float4*>(&As[k][ty*8+4]);
            *reinterpret_cast<float4*>(b)   = *reinterpret_cast<const float4*>(&Bs[k][tx*8]);
            *reinterpret_cast<float4*>(b+4) = *reinterpret_cast<const float4*>(&Bs[k][tx*8+4]);
#pragma unroll
            for (int i = 0; i < 8; i++)
#pragma unroll
                for (int j = 0; j < 8; j++)
                    acc[i][j] += a[i] * b[j];
        }
        __syncthreads();
    }

#pragma unroll
    for (int i = 0; i < 8; i++) {
        int row = bm + ty*8 + i;
#pragma unroll
        for (int j = 0; j < 8; j++) {
            int col = bn + tx*8 + j;
            float v = acc[i][j] * alpha;
            if (bias) v += bias[col];
            if (D)    v += D[(size_t)row * ldd + col];
            C[(size_t)row * ldc + col] = v;
        }
    }
}

// ---------------- RMSNorm (in place, row width CQLR) ----------------
__global__ __launch_bounds__(256) void rms_kernel(float* __restrict__ x, const float* __restrict__ w)
{
    __shared__ float red[8];
    size_t row = blockIdx.x;
    float* p = x + row * CQLR;
    int tid = threadIdx.x;
    float s = 0.f;
    for (int i = tid; i < CQLR; i += 256) { float v = p[i]; s += v * v; }
#pragma unroll
    for (int o = 16; o; o >>= 1) s += __shfl_xor_sync(~0u, s, o);
    if ((tid & 31) == 0) red[tid >> 5] = s;
    __syncthreads();
    float tot = 0.f;
#pragma unroll
    for (int i = 0; i < 8; i++) tot += red[i];
    float r = rsqrtf(tot + 1e-6f);
    for (int i = tid; i < CQLR; i += 256) p[i] = p[i] * r * w[i];
}

// ---------------- softmax over rows of length CS (in place) ----------------
__global__ __launch_bounds__(256) void softmax_kernel(float* __restrict__ x)
{
    __shared__ float red[8];
    size_t row = blockIdx.x;
    float* p = x + row * (size_t)CS;
    int tid = threadIdx.x;
    float vmax = -1e30f;
    for (int i = tid; i < CS; i += 256) vmax = fmaxf(vmax, p[i]);
#pragma unroll
    for (int o = 16; o; o >>= 1) vmax = fmaxf(vmax, __shfl_xor_sync(~0u, vmax, o));
    if ((tid & 31) == 0) red[tid >> 5] = vmax;
    __syncthreads();
    float m = -1e30f;
#pragma unroll
    for (int i = 0; i < 8; i++) m = fmaxf(m, red[i]);
    __syncthreads();
    float s = 0.f;
    for (int i = tid; i < CS; i += 256) { float e = __expf(p[i] - m); p[i] = e; s += e; }
#pragma unroll
    for (int o = 16; o; o >>= 1) s += __shfl_xor_sync(~0u, s, o);
    if ((tid & 31) == 0) red[tid >> 5] = s;
    __syncthreads();
    float tot = 0.f;
#pragma unroll
    for (int i = 0; i < 8; i++) tot += red[i];
    float inv = 1.f / tot;
    for (int i = tid; i < CS; i += 256) p[i] *= inv;
}

// ---------------- RoPE ----------------
__device__ __forceinline__ void rope_cs(int s, int i, float& c, float& sn)
{
    double invf = pow(10000.0, -(double)(2 * i) / 128.0);
    double ang = (double)s * invf;
    c = (float)cos(ang);
    sn = (float)sin(ang);
}

// k_pe: in place on g_ckv columns [512..640)
__global__ void rope_k_kernel(float* __restrict__ ckv)
{
    int idx = blockIdx.x * blockDim.x + threadIdx.x;   // CB*CS*64
    if (idx >= CB * CS * 64) return;
    int i = idx & 63;
    int row = idx >> 6;
    int s = row & (CS - 1);
    float c, sn; rope_cs(s, i, c, sn);
    float* p = ckv + (size_t)row * CCAT + CKVLR;
    float x1 = p[i], x2 = p[i + 64];
    p[i]      = x1 * c - x2 * sn;
    p[i + 64] = x2 * c + x1 * sn;
}

// q_pe: read from g_q [b,s,h,256] cols 128..255 -> write g_qcat [b,h,s,640] cols 512..639
__global__ void rope_q_kernel(const float* __restrict__ q, float* __restrict__ qcat)
{
    int idx = blockIdx.x * blockDim.x + threadIdx.x;   // CB*CS*CNH*64
    if (idx >= CB * CS * CNH * 64) return;
    int i = idx & 63;
    int h = (idx >> 6) & 15;
    int row = idx >> 10;              // b*CS + s
    int s = row & (CS - 1);
    int b = row >> 11;
    float c, sn; rope_cs(s, i, c, sn);
    const float* src = q + (size_t)row * (CNH * CQHD) + h * CQHD + CHD;
    float x1 = src[i], x2 = src[i + 64];
    float* dst = qcat + ((size_t)(b * CNH + h) * CS + s) * CCAT + CKVLR;
    dst[i]      = x1 * c - x2 * sn;
    dst[i + 64] = x2 * c + x1 * sn;
}

// extract q_absorb / o_absorb from kv_b_W [KVLR, NH, 2, HD] -> [h][c][d]
__global__ void extract_absorb_kernel(const float* __restrict__ kvb,
                                      float* __restrict__ qab, float* __restrict__ oab)
{
    int idx = blockIdx.x * blockDim.x + threadIdx.x;   // CKVLR*CNH*CHD
    if (idx >= CKVLR * CNH * CHD) return;
    int d = idx & 127;
    int h = (idx >> 7) & 15;
    int c = idx >> 11;
    const float* src = kvb + (((size_t)c * CNH + h) * 2) * CHD;
    size_t dst = ((size_t)h * CKVLR + c) * CHD + d;
    qab[dst] = src[d];
    oab[dst] = src[CHD + d];
}

// ---------------- launch ----------------
extern "C" void kernel_launch(void* const* d_in, const int* in_sizes, int n_in,
                              void* d_out, int out_size)
{
    const float* hidden = (const float*)d_in[0];
    const float* mask   = (const float*)d_in[1];
    const float* q_a_W  = (const float*)d_in[2];
    const float* q_a_b  = (const float*)d_in[3];
    const float* q_a_nw = (const float*)d_in[4];
    const float* q_b_W  = (const float*)d_in[5];
    const float* kv_a_W = (const float*)d_in[6];
    const float* kv_b_W = (const float*)d_in[7];
    const float* o_W    = (const float*)d_in[8];
    float* out = (float*)d_out;

    void* p;
    cudaGetSymbolAddress(&p, g_qa);      float* qa    = (float*)p;
    cudaGetSymbolAddress(&p, g_q);       float* qv    = (float*)p;
    cudaGetSymbolAddress(&p, g_ckv);     float* ckv   = (float*)p;
    cudaGetSymbolAddress(&p, g_qcat);    float* qcat  = (float*)p;
    cudaGetSymbolAddress(&p, g_scores);  float* sc    = (float*)p;
    cudaGetSymbolAddress(&p, g_outlat);  float* olat  = (float*)p;
    cudaGetSymbolAddress(&p, g_outhead); float* ohead = (float*)p;
    cudaGetSymbolAddress(&p, g_qab);     float* qab   = (float*)p;
    cudaGetSymbolAddress(&p, g_oab);     float* oab   = (float*)p;

    const long long LS = CS;

    // 1) q_a = hidden @ q_a_W^T + bias   [4096,1536]
    gemm_kernel<true><<<dim3(CQLR/128, CBS/128, 1), 256>>>(
        hidden, CHID, q_a_W, CHID, qa, CQLR, nullptr, 0, q_a_b,
        1.f, CHID, 1, 0,0,0,0,0,0,0,0);

    // 2) rmsnorm in place
    rms_kernel<<<CBS, 256>>>(qa, q_a_nw);

    // 3) q = qa_norm @ q_b_W^T   [4096,4096]
    gemm_kernel<true><<<dim3((CNH*CQHD)/128, CBS/128, 1), 256>>>(
        qa, CQLR, q_b_W, CQLR, qv, CNH*CQHD, nullptr, 0, nullptr,
        1.f, CQLR, 1, 0,0,0,0,0,0,0,0);

    // 4) ckv_full = hidden @ kv_a_W^T   [4096,640]
    gemm_kernel<true><<<dim3(CCAT/128, CBS/128, 1), 256>>>(
        hidden, CHID, kv_a_W, CHID, ckv, CCAT, nullptr, 0, nullptr,
        1.f, CHID, 1, 0,0,0,0,0,0,0,0);

    // 5) RoPE
    rope_k_kernel<<<(CB*CS*64)/256, 256>>>(ckv);
    rope_q_kernel<<<(CB*CS*CNH*64)/256, 256>>>(qv, qcat);

    // 6) extract absorb matrices
    extract_absorb_kernel<<<(CKVLR*CNH*CHD)/256, 256>>>(kv_b_W, qab, oab);

    // 7) q_lat[b,h,s,c] = q_nope . q_absorb  -> qcat[...,:512]   (NT, Z=32)
    gemm_kernel<true><<<dim3(CKVLR/128, CS/128, CB*CNH), 256>>>(
        qv, CNH*CQHD, qab, CHD, qcat, CCAT, nullptr, 0, nullptr,
        1.f, CHD, CNH,
        LS*CNH*CQHD, CQHD,                       // A: b -> S*4096, h -> 256
        0, (long long)CKVLR*CHD,                 // B: per-head absorb
        LS*CNH*CCAT, LS*CCAT,                    // C: [b,h,s,640]
        0, 0);

    // 8) scores = (qcat . ckv_cat^T)*scale + mask   (NT, Z=32)
    float scale = 1.f / sqrtf((float)CCAT);
    gemm_kernel<true><<<dim3(CS/128, CS/128, CB*CNH), 256>>>(
        qcat, CCAT, ckv, CCAT, sc, CS, mask, CS, nullptr,
        scale, CCAT, CNH,
        LS*CNH*CCAT, LS*CCAT,                    // A
        LS*CCAT, 0,                              // B: per-b keys
        LS*CNH*CS, LS*CS,                        // C
        LS*CS, 0);                               // D: mask per-b

    // 9) softmax rows
    softmax_kernel<<<CB*CNH*CS, 256>>>(sc);

    // 10) out_lat = attn @ ckv[:, :512]   (NN, Z=32)
    gemm_kernel<false><<<dim3(CKVLR/128, CS/128, CB*CNH), 256>>>(
        sc, CS, ckv, CCAT, olat, CKVLR, nullptr, 0, nullptr,
        1.f, CS, CNH,
        LS*CNH*CS, LS*CS,
        LS*CCAT, 0,
        LS*CNH*CKVLR, LS*CKVLR,
        0, 0);

    // 11) out_head[b,s,h*128+d] = out_lat . o_absorb   (NN, Z=32)
    gemm_kernel<false><<<dim3(CHD/128, CS/128, CB*CNH), 256>>>(
        olat, CKVLR, oab, CHD, ohead, CNH*CHD, nullptr, 0, nullptr,
        1.f, CKVLR, CNH,
        LS*CNH*CKVLR, LS*CKVLR,
        0, (long long)CKVLR*CHD,
        LS*CNH*CHD, CHD,
        0, 0);

    // 12) final = out_head @ o_W^T   [4096,2048]
    gemm_kernel<true><<<dim3(CHID/128, CBS/128, 1), 256>>>(
        ohead, CNH*CHD, o_W, CNH*CHD, out, CHID, nullptr, 0, nullptr,
        1.f, CNH*CHD, 1, 0,0,0,0,0,0,0,0);
}

// round 3
// speedup vs baseline: 1.9252x; 1.9252x over previous
#include <cuda_runtime.h>
#include <cuda_bf16.h>
#include <math.h>
#include <stdint.h>

// ---------------- problem constants ----------------
#define CB   2
#define CS   2048
#define CHID 2048
#define CNH  16
#define CHD  128
#define CQLR 1536
#define CKVLR 512
#define CBS  (CB*CS)          // 4096
#define CCAT (CKVLR+CHD)      // 640
#define CQHD (2*CHD)          // 256

typedef __nv_bfloat16 bf16;

// ---------------- device scratch ----------------
static __device__ __align__(256) float g_qa[(size_t)CBS*CQLR];
static __device__ __align__(256) float g_q [(size_t)CBS*CNH*CQHD];
static __device__ __align__(256) float g_ckv[(size_t)CBS*CCAT];
static __device__ __align__(256) float g_qcat[(size_t)CB*CNH*CS*CCAT];
static __device__ __align__(256) float g_scores[(size_t)CB*CNH*CS*CS];
static __device__ __align__(256) float g_olat[(size_t)CB*CNH*CS*CKVLR];
static __device__ __align__(256) float g_ohead[(size_t)CBS*CNH*CHD];

static __device__ __align__(256) bf16 g_hid_h[(size_t)CBS*CHID],  g_hid_l[(size_t)CBS*CHID];
static __device__ __align__(256) bf16 g_qaw_h[(size_t)CQLR*CHID], g_qaw_l[(size_t)CQLR*CHID];
static __device__ __align__(256) bf16 g_qbw_h[(size_t)CNH*CQHD*CQLR], g_qbw_l[(size_t)CNH*CQHD*CQLR];
static __device__ __align__(256) bf16 g_kvaw_h[(size_t)CCAT*CHID], g_kvaw_l[(size_t)CCAT*CHID];
static __device__ __align__(256) bf16 g_ow_h[(size_t)CHID*CNH*CHD], g_ow_l[(size_t)CHID*CNH*CHD];
static __device__ __align__(256) bf16 g_qan_h[(size_t)CBS*CQLR], g_qan_l[(size_t)CBS*CQLR];
static __device__ __align__(256) bf16 g_qs_h[(size_t)CBS*CNH*CQHD], g_qs_l[(size_t)CBS*CNH*CQHD];
static __device__ __align__(256) bf16 g_qab_h[(size_t)CNH*CKVLR*CHD], g_qab_l[(size_t)CNH*CKVLR*CHD];     // [h][c][d]
static __device__ __align__(256) bf16 g_oabt_h[(size_t)CNH*CHD*CKVLR], g_oabt_l[(size_t)CNH*CHD*CKVLR];   // [h][d][c]
static __device__ __align__(256) bf16 g_qc_h[(size_t)CB*CNH*CS*CCAT], g_qc_l[(size_t)CB*CNH*CS*CCAT];
static __device__ __align__(256) bf16 g_ckv_h[(size_t)CBS*CCAT], g_ckv_l[(size_t)CBS*CCAT];
static __device__ __align__(256) bf16 g_ckvt_h[(size_t)CB*CKVLR*CS], g_ckvt_l[(size_t)CB*CKVLR*CS];       // [b][c][t]
static __device__ __align__(256) bf16 g_att_h[(size_t)CB*CNH*CS*CS], g_att_l[(size_t)CB*CNH*CS*CS];
static __device__ __align__(256) bf16 g_ol_h[(size_t)CB*CNH*CS*CKVLR], g_ol_l[(size_t)CB*CNH*CS*CKVLR];
static __device__ __align__(256) bf16 g_oh_h[(size_t)CBS*CNH*CHD], g_oh_l[(size_t)CBS*CNH*CHD];

// ---------------- asm helpers (all sm_80-portable) ----------------
__device__ __forceinline__ uint32_t smem_u32(const void* p) {
    uint32_t a;
    asm("{ .reg .u64 t; cvta.to.shared.u64 t, %1; cvt.u32.u64 %0, t; }" : "=r"(a) : "l"(p));
    return a;
}
#define CP_ASYNC16(dst, src) \
    asm volatile("cp.async.cg.shared.global [%0], [%1], 16;" :: "r"(dst), "l"(src) : "memory")
#define CP_COMMIT() asm volatile("cp.async.commit_group;" ::: "memory")
#define CP_WAIT(n)  asm volatile("cp.async.wait_group %0;" :: "n"(n) : "memory")

#define LDSM4(r, addr) \
    asm volatile("ldmatrix.sync.aligned.m8n8.x4.shared.b16 {%0,%1,%2,%3}, [%4];" \
        : "=r"((r)[0]),"=r"((r)[1]),"=r"((r)[2]),"=r"((r)[3]) : "r"(addr))

#define MMA16816(d, a, b0, b1) \
    asm volatile("mma.sync.aligned.m16n8k16.row.col.f32.bf16.bf16.f32 " \
        "{%0,%1,%2,%3},{%4,%5,%6,%7},{%8,%9},{%0,%1,%2,%3};" \
        : "+f"((d)[0]),"+f"((d)[1]),"+f"((d)[2]),"+f"((d)[3]) \
        : "r"((a)[0]),"r"((a)[1]),"r"((a)[2]),"r"((a)[3]), "r"(b0),"r"(b1))

// ---------------- bf16 hi/lo split MMA GEMM ----------------
// C[m,n] = alpha*sum_k A[m,k]*B[n,k] (+bias[n]) (+D[m,n]); A,B bf16 hi/lo, K-major.
// Block 128x128, K-chunk 32, 8 warps (4m x 2n), warp tile 32x64.
static constexpr int GBM = 128, GBN = 128, GBK = 32, STAGES = 4;
static constexpr int ASZ = GBM * GBK * 2;            // 8192 B per A sub-tile
static constexpr int STAGE_B = 4 * ASZ;              // Ah,Al,Bh,Bl = 32KB
static constexpr size_t GSMEM = (size_t)STAGES * STAGE_B;  // 128KB

__device__ __forceinline__ uint32_t swz(int row, int ch) {
    return (uint32_t)(row * 64 + ((ch ^ ((row >> 1) & 3)) * 16));
}

__global__ __launch_bounds__(256, 1) void mma_gemm(
    const bf16* __restrict__ Ah, const bf16* __restrict__ Al, int lda, long long aO, long long aI,
    const bf16* __restrict__ Bh, const bf16* __restrict__ Bl, int ldb, long long bO, long long bI,
    float* __restrict__ C, int ldc, long long cO, long long cI,
    const float* __restrict__ D, int ldd, long long dO, long long dI,
    const float* __restrict__ bias, float alpha, int K, int zInner)
{
    extern __shared__ char smem_raw[];
    uint32_t sbase = smem_u32(smem_raw);

    int tid = threadIdx.x, wid = tid >> 5, lane = tid & 31;
    int z = blockIdx.z, zo = z / zInner, zi = z - zo * zInner;
    Ah += zo * aO + zi * aI;  Al += zo * aO + zi * aI;
    Bh += zo * bO + zi * bI;  Bl += zo * bO + zi * bI;
    C  += zo * cO + zi * cI;
    if (D) D += zo * dO + zi * dI;

    int bm = blockIdx.y * GBM, bn = blockIdx.x * GBN;
    int wm = (wid & 3) * 32;     // warp m offset
    int wn = (wid >> 2) * 64;    // warp n offset

    const bf16* pAh = Ah + (long long)bm * lda;
    const bf16* pAl = Al + (long long)bm * lda;
    const bf16* pBh = Bh + (long long)bn * ldb;
    const bf16* pBl = Bl + (long long)bn * ldb;

    // per-thread load coords: 512 16B-chunks per sub-tile, 2 per thread
    int r0c = (tid * 2) >> 2,        ch0 = (tid * 2) & 3;
    int r1c = (tid * 2 + 1) >> 2,    ch1 = (tid * 2 + 1) & 3;
    uint32_t so0 = swz(r0c, ch0), so1 = swz(r1c, ch1);

    float acc[2][8][4];
#pragma unroll
    for (int t = 0; t < 2; t++)
#pragma unroll
        for (int j = 0; j < 8; j++)
#pragma unroll
            for (int q = 0; q < 4; q++) acc[t][j][q] = 0.f;

    int nk = K / GBK;

#define ISSUE(stage_) do { \
    int st_ = (stage_) % STAGES; \
    uint32_t sb_ = sbase + st_ * STAGE_B; \
    long long k0_ = (long long)(stage_) * GBK; \
    CP_ASYNC16(sb_ + so0,           pAh + (long long)r0c * lda + k0_ + ch0 * 8); \
    CP_ASYNC16(sb_ + so1,           pAh + (long long)r1c * lda + k0_ + ch1 * 8); \
    CP_ASYNC16(sb_ + ASZ + so0,     pAl + (long long)r0c * lda + k0_ + ch0 * 8); \
    CP_ASYNC16(sb_ + ASZ + so1,     pAl + (long long)r1c * lda + k0_ + ch1 * 8); \
    CP_ASYNC16(sb_ + 2*ASZ + so0,   pBh + (long long)r0c * ldb + k0_ + ch0 * 8); \
    CP_ASYNC16(sb_ + 2*ASZ + so1,   pBh + (long long)r1c * ldb + k0_ + ch1 * 8); \
    CP_ASYNC16(sb_ + 3*ASZ + so0,   pBl + (long long)r0c * ldb + k0_ + ch0 * 8); \
    CP_ASYNC16(sb_ + 3*ASZ + so1,   pBl + (long long)r1c * ldb + k0_ + ch1 * 8); \
} while (0)

    // prefetch
    for (int s = 0; s < STAGES - 1; s++) {
        if (s < nk) ISSUE(s);
        CP_COMMIT();
    }

    // precomputed ldmatrix lane geometry
    int a_row = (lane & 15);           // + wm + t*16
    int a_sel = lane >> 4;             // 0/1 -> which 16B half of k16
    int b_g   = lane >> 3;
    int b_row = (lane & 7) + ((b_g >> 1) * 8);   // + wn + j16*16
    int b_sel = b_g & 1;

    for (int i = 0; i < nk; i++) {
        if (i + STAGES - 1 < nk) ISSUE(i + STAGES - 1);
        CP_COMMIT();
        CP_WAIT(STAGES - 1);
        __syncthreads();

        uint32_t sb = sbase + (i % STAGES) * STAGE_B;

#pragma unroll
        for (int kh = 0; kh < 2; kh++) {
            uint32_t Afh[2][4], Afl[2][4];
#pragma unroll
            for (int t = 0; t < 2; t++) {
                int row = wm + t * 16 + a_row;
                int ck = 2 * kh + a_sel;
                uint32_t off = swz(row, ck);
                LDSM4(Afh[t], sb + off);
                LDSM4(Afl[t], sb + ASZ + off);
            }
            uint32_t Bfh[4][4], Bfl[4][4];
#pragma unroll
            for (int j = 0; j < 4; j++) {
                int row = wn + j * 16 + b_row;
                int ck = 2 * kh + b_sel;
                uint32_t off = swz(row, ck);
                LDSM4(Bfh[j], sb + 2 * ASZ + off);
                LDSM4(Bfl[j], sb + 3 * ASZ + off);
            }
#pragma unroll
            for (int t = 0; t < 2; t++)
#pragma unroll
                for (int j = 0; j < 4; j++) {
                    MMA16816(acc[t][2*j],   Afh[t], Bfh[j][0], Bfh[j][1]);
                    MMA16816(acc[t][2*j],   Afh[t], Bfl[j][0], Bfl[j][1]);
                    MMA16816(acc[t][2*j],   Afl[t], Bfh[j][0], Bfh[j][1]);
                    MMA16816(acc[t][2*j+1], Afh[t], Bfh[j][2], Bfh[j][3]);
                    MMA16816(acc[t][2*j+1], Afh[t], Bfl[j][2], Bfl[j][3]);
                    MMA16816(acc[t][2*j+1], Afl[t], Bfh[j][2], Bfh[j][3]);
                }
        }
        __syncthreads();
    }
#undef ISSUE

    // epilogue
#pragma unroll
    for (int t = 0; t < 2; t++) {
        int r0 = bm + wm + t * 16 + (lane >> 2);
#pragma unroll
        for (int j = 0; j < 8; j++) {
            int col = bn + wn + j * 8 + (lane & 3) * 2;
            float v0 = acc[t][j][0] * alpha;
            float v1 = acc[t][j][1] * alpha;
            float v2 = acc[t][j][2] * alpha;
            float v3 = acc[t][j][3] * alpha;
            if (bias) { v0 += bias[col]; v1 += bias[col + 1]; v2 += bias[col]; v3 += bias[col + 1]; }
            if (D) {
                v0 += D[(long long)r0 * ldd + col];
                v1 += D[(long long)r0 * ldd + col + 1];
                v2 += D[(long long)(r0 + 8) * ldd + col];
                v3 += D[(long long)(r0 + 8) * ldd + col + 1];
            }
            C[(long long)r0 * ldc + col]           = v0;
            C[(long long)r0 * ldc + col + 1]       = v1;
            C[(long long)(r0 + 8) * ldc + col]     = v2;
            C[(long long)(r0 + 8) * ldc + col + 1] = v3;
        }
    }
}

// ---------------- split conversion ----------------
__device__ __forceinline__ void split2(float v, bf16* hp, bf16* lp) {
    bf16 h = __float2bfloat16(v);
    *hp = h;
    *lp = __float2bfloat16(v - __bfloat162float(h));
}

__global__ void cvt_split_kernel(const float* __restrict__ s, bf16* __restrict__ hi, bf16* __restrict__ lo, long long n)
{
    long long i = (long long)blockIdx.x * blockDim.x + threadIdx.x;
    long long st = (long long)gridDim.x * blockDim.x;
    for (; i < n; i += st) split2(s[i], hi + i, lo + i);
}

// qab [h][c][d], oabT [h][d][c] from kv_b_W [c, h, 2, d]
__global__ void extract_kernel(const float* __restrict__ kvb,
                               bf16* __restrict__ qh, bf16* __restrict__ ql,
                               bf16* __restrict__ oh, bf16* __restrict__ ol)
{
    long long n = (long long)CNH * CKVLR * CHD;
    long long i = (long long)blockIdx.x * blockDim.x + threadIdx.x;
    long long st = (long long)gridDim.x * blockDim.x;
    for (; i < n; i += st) {
        { // oabT: [h][d][c]
            int c = (int)(i & 511);
            int d = (int)((i >> 9) & 127);
            int h = (int)(i >> 16);
            float v = kvb[(((long long)c * CNH + h) * 2 + 1) * CHD + d];
            split2(v, oh + i, ol + i);
        }
        { // qab: [h][c][d]
            int d = (int)(i & 127);
            int c = (int)((i >> 7) & 511);
            int h = (int)(i >> 16);
            float v = kvb[(((long long)c * CNH + h) * 2) * CHD + d];
            split2(v, qh + i, ql + i);
        }
    }
}

// ckvT [b][c(512)][t(2048)] from ckv [b,t,640]
__global__ void cvt_ckvt_kernel(const float* __restrict__ ckv, bf16* __restrict__ hi, bf16* __restrict__ lo)
{
    long long n = (long long)CB * CKVLR * CS;
    long long i = (long long)blockIdx.x * blockDim.x + threadIdx.x;
    long long st = (long long)gridDim.x * blockDim.x;
    for (; i < n; i += st) {
        int t = (int)(i & 2047);
        int c = (int)((i >> 11) & 511);
        int b = (int)(i >> 20);
        float v = ckv[((long long)b * CS + t) * CCAT + c];
        split2(v, hi + i, lo + i);
    }
}

// ---------------- RMSNorm ----------------
__global__ __launch_bounds__(256) void rms_kernel(float* __restrict__ x, const float* __restrict__ w)
{
    __shared__ float red[8];
    size_t row = blockIdx.x;
    float* p = x + row * CQLR;
    int tid = threadIdx.x;
    float s = 0.f;
    for (int i = tid; i < CQLR; i += 256) { float v = p[i]; s += v * v; }
#pragma unroll
    for (int o = 16; o; o >>= 1) s += __shfl_xor_sync(~0u, s, o);
    if ((tid & 31) == 0) red[tid >> 5] = s;
    __syncthreads();
    float tot = 0.f;
#pragma unroll
    for (int i = 0; i < 8; i++) tot += red[i];
    float r = rsqrtf(tot + 1e-6f);
    for (int i = tid; i < CQLR; i += 256) p[i] = p[i] * r * w[i];
}

// ---------------- softmax + bf16 split ----------------
__global__ __launch_bounds__(256) void softmax_split_kernel(const float* __restrict__ x,
                                                            bf16* __restrict__ hi, bf16* __restrict__ lo)
{
    __shared__ float red[8];
    size_t row = blockIdx.x;
    const float* p = x + row * (size_t)CS;
    int tid = threadIdx.x;
    float vmax = -1e30f;
    for (int i = tid; i < CS; i += 256) vmax = fmaxf(vmax, p[i]);
#pragma unroll
    for (int o = 16; o; o >>= 1) vmax = fmaxf(vmax, __shfl_xor_sync(~0u, vmax, o));
    if ((tid & 31) == 0) red[tid >> 5] = vmax;
    __syncthreads();
    float m = -1e30f;
#pragma unroll
    for (int i = 0; i < 8; i++) m = fmaxf(m, red[i]);
    __syncthreads();
    float s = 0.f;
    for (int i = tid; i < CS; i += 256) s += __expf(p[i] - m);
#pragma unroll
    for (int o = 16; o; o >>= 1) s += __shfl_xor_sync(~0u, s, o);
    if ((tid & 31) == 0) red[tid >> 5] = s;
    __syncthreads();
    float tot = 0.f;
#pragma unroll
    for (int i = 0; i < 8; i++) tot += red[i];
    float inv = 1.f / tot;
    bf16* ph = hi + row * (size_t)CS;
    bf16* pl = lo + row * (size_t)CS;
    for (int i = tid; i < CS; i += 256) {
        float e = __expf(p[i] - m) * inv;
        split2(e, ph + i, pl + i);
    }
}

// ---------------- RoPE ----------------
__device__ __forceinline__ void rope_cs(int s, int i, float& c, float& sn)
{
    double invf = pow(10000.0, -(double)(2 * i) / 128.0);
    double ang = (double)s * invf;
    c = (float)cos(ang);
    sn = (float)sin(ang);
}

__global__ void rope_k_kernel(float* __restrict__ ckv)
{
    int idx = blockIdx.x * blockDim.x + threadIdx.x;
    if (idx >= CB * CS * 64) return;
    int i = idx & 63;
    int row = idx >> 6;
    int s = row & (CS - 1);
    float c, sn; rope_cs(s, i, c, sn);
    float* p = ckv + (size_t)row * CCAT + CKVLR;
    float x1 = p[i], x2 = p[i + 64];
    p[i]      = x1 * c - x2 * sn;
    p[i + 64] = x2 * c + x1 * sn;
}

__global__ void rope_q_kernel(const float* __restrict__ q, float* __restrict__ qcat)
{
    int idx = blockIdx.x * blockDim.x + threadIdx.x;
    if (idx >= CB * CS * CNH * 64) return;
    int i = idx & 63;
    int h = (idx >> 6) & 15;
    int row = idx >> 10;
    int s = row & (CS - 1);
    int b = row >> 11;
    float c, sn; rope_cs(s, i, c, sn);
    const float* src = q + (size_t)row * (CNH * CQHD) + h * CQHD + CHD;
    float x1 = src[i], x2 = src[i + 64];
    float* dst = qcat + ((size_t)(b * CNH + h) * CS + s) * CCAT + CKVLR;
    dst[i]      = x1 * c - x2 * sn;
    dst[i + 64] = x2 * c + x1 * sn;
}

// ---------------- launch ----------------
extern "C" void kernel_launch(void* const* d_in, const int* in_sizes, int n_in,
                              void* d_out, int out_size)
{
    const float* hidden = (const float*)d_in[0];
    const float* mask   = (const float*)d_in[1];
    const float* q_a_W  = (const float*)d_in[2];
    const float* q_a_b  = (const float*)d_in[3];
    const float* q_a_nw = (const float*)d_in[4];
    const float* q_b_W  = (const float*)d_in[5];
    const float* kv_a_W = (const float*)d_in[6];
    const float* kv_b_W = (const float*)d_in[7];
    const float* o_W    = (const float*)d_in[8];
    float* out = (float*)d_out;

    void* p;
#define SYM(v, g) cudaGetSymbolAddress(&p, g); auto* v = (decltype(&g[0]))p
    SYM(qa, g_qa);     SYM(qv, g_q);       SYM(ckv, g_ckv);   SYM(qcat, g_qcat);
    SYM(sc, g_scores); SYM(olat, g_olat);  SYM(ohead, g_ohead);
    SYM(hidh, g_hid_h); SYM(hidl, g_hid_l);
    SYM(qawh, g_qaw_h); SYM(qawl, g_qaw_l);
    SYM(qbwh, g_qbw_h); SYM(qbwl, g_qbw_l);
    SYM(kvawh, g_kvaw_h); SYM(kvawl, g_kvaw_l);
    SYM(owh, g_ow_h);   SYM(owl, g_ow_l);
    SYM(qanh, g_qan_h); SYM(qanl, g_qan_l);
    SYM(qsh, g_qs_h);   SYM(qsl, g_qs_l);
    SYM(qabh, g_qab_h); SYM(qabl, g_qab_l);
    SYM(oabth, g_oabt_h); SYM(oabtl, g_oabt_l);
    SYM(qch, g_qc_h);   SYM(qcl, g_qc_l);
    SYM(ckvh, g_ckv_h); SYM(ckvl, g_ckv_l);
    SYM(ckvth, g_ckvt_h); SYM(ckvtl, g_ckvt_l);
    SYM(atth, g_att_h); SYM(attl, g_att_l);
    SYM(olh, g_ol_h);   SYM(oll, g_ol_l);
    SYM(ohh, g_oh_h);   SYM(ohl, g_oh_l);
#undef SYM

    cudaFuncSetAttribute(mma_gemm, cudaFuncAttributeMaxDynamicSharedMemorySize, (int)GSMEM);

    const long long LS = CS;
    const int CVG = 2048;

    cvt_split_kernel<<<CVG, 256>>>(hidden, hidh, hidl, (long long)CBS * CHID);
    cvt_split_kernel<<<CVG, 256>>>(q_a_W, qawh, qawl, (long long)CQLR * CHID);
    cvt_split_kernel<<<CVG, 256>>>(q_b_W, qbwh, qbwl, (long long)CNH * CQHD * CQLR);
    cvt_split_kernel<<<CVG, 256>>>(o_W, owh, owl, (long long)CHID * CNH * CHD);
    cvt_split_kernel<<<CVG, 256>>>(kv_a_W, kvawh, kvawl, (long long)CCAT * CHID);
    extract_kernel<<<CVG, 256>>>(kv_b_W, qabh, qabl, oabth, oabtl);

    // 1) q_a = hidden @ q_a_W^T + bias   [4096,1536] K=2048
    mma_gemm<<<dim3(CQLR / GBN, CBS / GBM, 1), 256, GSMEM>>>(
        hidh, hidl, CHID, 0, 0, qawh, qawl, CHID, 0, 0,
        qa, CQLR, 0, 0, nullptr, 0, 0, 0, q_a_b, 1.f, CHID, 1);

    // 2) rmsnorm + split
    rms_kernel<<<CBS, 256>>>(qa, q_a_nw);
    cvt_split_kernel<<<CVG, 256>>>(qa, qanh, qanl, (long long)CBS * CQLR);

    // 3) q = qa_norm @ q_b_W^T   [4096,4096] K=1536
    mma_gemm<<<dim3((CNH * CQHD) / GBN, CBS / GBM, 1), 256, GSMEM>>>(
        qanh, qanl, CQLR, 0, 0, qbwh, qbwl, CQLR, 0, 0,
        qv, CNH * CQHD, 0, 0, nullptr, 0, 0, 0, nullptr, 1.f, CQLR, 1);

    // 4) ckv = hidden @ kv_a_W^T   [4096,640] K=2048
    mma_gemm<<<dim3(CCAT / GBN, CBS / GBM, 1), 256, GSMEM>>>(
        hidh, hidl, CHID, 0, 0, kvawh, kvawl, CHID, 0, 0,
        ckv, CCAT, 0, 0, nullptr, 0, 0, 0, nullptr, 1.f, CHID, 1);

    // 5) RoPE
    rope_k_kernel<<<(CB * CS * 64) / 256, 256>>>(ckv);
    rope_q_kernel<<<(CB * CS * CNH * 64) / 256, 256>>>(qv, qcat);

    // 6) split q
    cvt_split_kernel<<<CVG, 256>>>(qv, qsh, qsl, (long long)CBS * CNH * CQHD);

    // 7) q_lat -> qcat cols [0,512)   K=128, Z=32
    mma_gemm<<<dim3(CKVLR / GBN, CS / GBM, CB * CNH), 256, GSMEM>>>(
        qsh, qsl, CNH * CQHD, LS * CNH * CQHD, CQHD,
        qabh, qabl, CHD, 0, (long long)CKVLR * CHD,
        qcat, CCAT, LS * CNH * CCAT, LS * CCAT,
        nullptr, 0, 0, 0, nullptr, 1.f, CHD, CNH);

    // 8) splits for attention
    cvt_split_kernel<<<CVG, 256>>>(ckv, ckvh, ckvl, (long long)CBS * CCAT);
    cvt_ckvt_kernel<<<CVG, 256>>>(ckv, ckvth, ckvtl);
    cvt_split_kernel<<<CVG, 256>>>(qcat, qch, qcl, (long long)CB * CNH * CS * CCAT);

    // 9) scores = (qcat . ckv^T)*scale + mask   K=640, Z=32
    float scale = 1.f / sqrtf((float)CCAT);
    mma_gemm<<<dim3(CS / GBN, CS / GBM, CB * CNH), 256, GSMEM>>>(
        qch, qcl, CCAT, LS * CNH * CCAT, LS * CCAT,
        ckvh, ckvl, CCAT, LS * CCAT, 0,
        sc, CS, LS * CNH * CS, LS * CS,
        mask, CS, LS * CS, 0, nullptr, scale, CCAT, CNH);

    // 10) softmax + split
    softmax_split_kernel<<<CB * CNH * CS, 256>>>(sc, atth, attl);

    // 11) out_lat = attn @ ckv[:, :512]   K=2048, Z=32 (via ckvT, NT)
    mma_gemm<<<dim3(CKVLR / GBN, CS / GBM, CB * CNH), 256, GSMEM>>>(
        atth, attl, CS, LS * CNH * CS, LS * CS,
        ckvth, ckvtl, CS, (long long)CKVLR * CS, 0,
        olat, CKVLR, LS * CNH * CKVLR, LS * CKVLR,
        nullptr, 0, 0, 0, nullptr, 1.f, CS, CNH);

    // 12) split olat
    cvt_split_kernel<<<CVG, 256>>>(olat, olh, oll, (long long)CB * CNH * CS * CKVLR);

    // 13) out_head = olat . o_absorb^T -> [b,s,h*128+d]   K=512, N=128, Z=32
    mma_gemm<<<dim3(1, CS / GBM, CB * CNH), 256, GSMEM>>>(
        olh, oll, CKVLR, LS * CNH * CKVLR, LS * CKVLR,
        oabth, oabtl, CKVLR, 0, (long long)CHD * CKVLR,
        ohead, CNH * CHD, LS * (long long)CNH * CHD, CHD,
        nullptr, 0, 0, 0, nullptr, 1.f, CKVLR, CNH);

    // 14) split ohead
    cvt_split_kernel<<<CVG, 256>>>(ohead, ohh, ohl, (long long)CBS * CNH * CHD);

    // 15) final = ohead @ o_W^T   [4096,2048] K=2048
    mma_gemm<<<dim3(CHID / GBN, CBS / GBM, 1), 256, GSMEM>>>(
        ohh, ohl, CNH * CHD, 0, 0, owh, owl, CNH * CHD, 0, 0,
        out, CHID, 0, 0, nullptr, 0, 0, 0, nullptr, 1.f, CNH * CHD, 1);
}

// round 4
// speedup vs baseline: 2.3893x; 1.2411x over previous
#include <cuda_runtime.h>
#include <cuda_bf16.h>
#include <math.h>
#include <stdint.h>

// ---------------- problem constants ----------------
#define CB   2
#define CS   2048
#define CHID 2048
#define CNH  16
#define CHD  128
#define CQLR 1536
#define CKVLR 512
#define CBS  (CB*CS)          // 4096
#define CCAT (CKVLR+CHD)      // 640
#define CQHD (2*CHD)          // 256

typedef __nv_bfloat16 bf16;

// ---------------- device scratch ----------------
static __device__ __align__(256) float g_qa[(size_t)CBS*CQLR];
static __device__ __align__(256) float g_ckv[(size_t)CBS*CCAT];
static __device__ __align__(256) float g_scores[(size_t)CB*CNH*CS*CS];

static __device__ __align__(256) bf16 g_hid_h[(size_t)CBS*CHID],  g_hid_l[(size_t)CBS*CHID];
static __device__ __align__(256) bf16 g_qaw_h[(size_t)CQLR*CHID], g_qaw_l[(size_t)CQLR*CHID];
static __device__ __align__(256) bf16 g_qbw_h[(size_t)CNH*CQHD*CQLR], g_qbw_l[(size_t)CNH*CQHD*CQLR];
static __device__ __align__(256) bf16 g_kvaw_h[(size_t)CCAT*CHID], g_kvaw_l[(size_t)CCAT*CHID];
static __device__ __align__(256) bf16 g_ow_h[(size_t)CHID*CNH*CHD], g_ow_l[(size_t)CHID*CNH*CHD];
static __device__ __align__(256) bf16 g_qan_h[(size_t)CBS*CQLR], g_qan_l[(size_t)CBS*CQLR];
static __device__ __align__(256) bf16 g_qs_h[(size_t)CBS*CNH*CQHD], g_qs_l[(size_t)CBS*CNH*CQHD];
static __device__ __align__(256) bf16 g_qab_h[(size_t)CNH*CKVLR*CHD], g_qab_l[(size_t)CNH*CKVLR*CHD];     // [h][c][d]
static __device__ __align__(256) bf16 g_oabt_h[(size_t)CNH*CHD*CKVLR], g_oabt_l[(size_t)CNH*CHD*CKVLR];   // [h][d][c]
static __device__ __align__(256) bf16 g_qc_h[(size_t)CB*CNH*CS*CCAT], g_qc_l[(size_t)CB*CNH*CS*CCAT];
static __device__ __align__(256) bf16 g_ckv_h[(size_t)CBS*CCAT], g_ckv_l[(size_t)CBS*CCAT];
static __device__ __align__(256) bf16 g_ckvt_h[(size_t)CB*CKVLR*CS], g_ckvt_l[(size_t)CB*CKVLR*CS];       // [b][c][t]
static __device__ __align__(256) bf16 g_att_h[(size_t)CB*CNH*CS*CS], g_att_l[(size_t)CB*CNH*CS*CS];
static __device__ __align__(256) bf16 g_ol_h[(size_t)CB*CNH*CS*CKVLR], g_ol_l[(size_t)CB*CNH*CS*CKVLR];
static __device__ __align__(256) bf16 g_oh_h[(size_t)CBS*CNH*CHD], g_oh_l[(size_t)CBS*CNH*CHD];

// ---------------- asm helpers (sm_80-portable) ----------------
__device__ __forceinline__ uint32_t smem_u32(const void* p) {
    uint32_t a;
    asm("{ .reg .u64 t; cvta.to.shared.u64 t, %1; cvt.u32.u64 %0, t; }" : "=r"(a) : "l"(p));
    return a;
}
#define CP_ASYNC16(dst, src) \
    asm volatile("cp.async.cg.shared.global [%0], [%1], 16;" :: "r"(dst), "l"(src) : "memory")
#define CP_COMMIT() asm volatile("cp.async.commit_group;" ::: "memory")
#define CP_WAIT(n)  asm volatile("cp.async.wait_group %0;" :: "n"(n) : "memory")

#define LDSM4(r, addr) \
    asm volatile("ldmatrix.sync.aligned.m8n8.x4.shared.b16 {%0,%1,%2,%3}, [%4];" \
        : "=r"((r)[0]),"=r"((r)[1]),"=r"((r)[2]),"=r"((r)[3]) : "r"(addr))

#define MMA16816(d, a, b0, b1) \
    asm volatile("mma.sync.aligned.m16n8k16.row.col.f32.bf16.bf16.f32 " \
        "{%0,%1,%2,%3},{%4,%5,%6,%7},{%8,%9},{%0,%1,%2,%3};" \
        : "+f"((d)[0]),"+f"((d)[1]),"+f"((d)[2]),"+f"((d)[3]) \
        : "r"((a)[0]),"r"((a)[1]),"r"((a)[2]),"r"((a)[3]), "r"(b0),"r"(b1))

__device__ __forceinline__ void split2(float v, bf16* hp, bf16* lp) {
    bf16 h = __float2bfloat16(v);
    *hp = h;
    *lp = __float2bfloat16(v - __bfloat162float(h));
}
__device__ __forceinline__ void split2x2(float v0, float v1, bf16* hp, bf16* lp) {
    bf16 h0 = __float2bfloat16(v0), h1 = __float2bfloat16(v1);
    bf16 l0 = __float2bfloat16(v0 - __bfloat162float(h0));
    bf16 l1 = __float2bfloat16(v1 - __bfloat162float(h1));
    __nv_bfloat162 hh; hh.x = h0; hh.y = h1;
    __nv_bfloat162 ll; ll.x = l0; ll.y = l1;
    *reinterpret_cast<__nv_bfloat162*>(hp) = hh;
    *reinterpret_cast<__nv_bfloat162*>(lp) = ll;
}

// ---------------- bf16 hi/lo split MMA GEMM ----------------
// C[m,n] = alpha*sum_k A[m,k]*B[n,k] (+bias[n]) (+D[m,n]); A,B bf16 hi/lo, K-major.
// BN=128: 8 warps 4mx2n, warp 32x64.   BN=256: 8 warps 2mx4n, warp 64x64.
static constexpr int GBK = 32, STAGES = 4;
static constexpr int ASZ = 128 * GBK * 2;   // 8192 B

__device__ __forceinline__ uint32_t swz(int row, int ch) {
    return (uint32_t)(row * 64 + ((ch ^ ((row >> 1) & 3)) * 16));
}

template<int BN>
__global__ __launch_bounds__(256, 1) void mma_gemm(
    const bf16* __restrict__ Ah, const bf16* __restrict__ Al, int lda, long long aO, long long aI,
    const bf16* __restrict__ Bh, const bf16* __restrict__ Bl, int ldb, long long bO, long long bI,
    float* __restrict__ C, bf16* __restrict__ Chi, bf16* __restrict__ Clo,
    int ldc, long long cO, long long cI,
    const float* __restrict__ D, int ldd, long long dO, long long dI,
    const float* __restrict__ bias, float alpha, int K, int zInner)
{
    constexpr int TM = (BN == 256) ? 4 : 2;
    constexpr int BSZ = BN * GBK * 2;
    constexpr int BCH = BN * 4;               // 16B chunks per B sub-tile
    constexpr int STAGE_B = 2 * ASZ + 2 * BSZ;

    extern __shared__ char smem_raw[];
    uint32_t sbase = smem_u32(smem_raw);

    int tid = threadIdx.x, wid = tid >> 5, lane = tid & 31;
    int z = blockIdx.z, zo = z / zInner, zi = z - zo * zInner;
    Ah += zo * aO + zi * aI;  Al += zo * aO + zi * aI;
    Bh += zo * bO + zi * bI;  Bl += zo * bO + zi * bI;
    if (C)   C   += zo * cO + zi * cI;
    if (Chi) { Chi += zo * cO + zi * cI; Clo += zo * cO + zi * cI; }
    if (D) D += zo * dO + zi * dI;

    int bm = blockIdx.y * 128, bn = blockIdx.x * BN;
    int wm, wn;
    if (BN == 256) { wm = (wid & 1) * 64; wn = (wid >> 1) * 64; }
    else           { wm = (wid & 3) * 32; wn = (wid >> 2) * 64; }

    const bf16* pAh = Ah + (long long)bm * lda;
    const bf16* pAl = Al + (long long)bm * lda;
    const bf16* pBh = Bh + (long long)bn * ldb;
    const bf16* pBl = Bl + (long long)bn * ldb;

    float acc[TM][8][4];
#pragma unroll
    for (int t = 0; t < TM; t++)
#pragma unroll
        for (int j = 0; j < 8; j++)
#pragma unroll
            for (int q = 0; q < 4; q++) acc[t][j][q] = 0.f;

    int nk = K / GBK;

#define ISSUE(stage_) do { \
    int st_ = (stage_) % STAGES; \
    uint32_t sb_ = sbase + st_ * STAGE_B; \
    long long k0_ = (long long)(stage_) * GBK; \
    _Pragma("unroll") \
    for (int u = 0; u < 2; u++) { \
        int idx = u * 256 + tid; int r = idx >> 2, ch = idx & 3; \
        uint32_t so = swz(r, ch); \
        CP_ASYNC16(sb_ + so,       pAh + (long long)r * lda + k0_ + ch * 8); \
        CP_ASYNC16(sb_ + ASZ + so, pAl + (long long)r * lda + k0_ + ch * 8); \
    } \
    _Pragma("unroll") \
    for (int u = 0; u < BCH / 256; u++) { \
        int idx = u * 256 + tid; int r = idx >> 2, ch = idx & 3; \
        uint32_t so = swz(r, ch); \
        CP_ASYNC16(sb_ + 2 * ASZ + so,       pBh + (long long)r * ldb + k0_ + ch * 8); \
        CP_ASYNC16(sb_ + 2 * ASZ + BSZ + so, pBl + (long long)r * ldb + k0_ + ch * 8); \
    } \
} while (0)

    for (int s = 0; s < STAGES - 1; s++) {
        if (s < nk) ISSUE(s);
        CP_COMMIT();
    }

    int a_row = (lane & 15);
    int a_sel = lane >> 4;
    int b_g   = lane >> 3;
    int b_row = (lane & 7) + ((b_g >> 1) * 8);
    int b_sel = b_g & 1;

    for (int i = 0; i < nk; i++) {
        if (i + STAGES - 1 < nk) ISSUE(i + STAGES - 1);
        CP_COMMIT();
        CP_WAIT(STAGES - 1);
        __syncthreads();

        uint32_t sb = sbase + (i % STAGES) * STAGE_B;

#pragma unroll
        for (int kh = 0; kh < 2; kh++) {
            uint32_t Afh[TM][4], Afl[TM][4];
#pragma unroll
            for (int t = 0; t < TM; t++) {
                int row = wm + t * 16 + a_row;
                int ck = 2 * kh + a_sel;
                uint32_t off = swz(row, ck);
                LDSM4(Afh[t], sb + off);
                LDSM4(Afl[t], sb + ASZ + off);
            }
            uint32_t Bfh[4][4], Bfl[4][4];
#pragma unroll
            for (int j = 0; j < 4; j++) {
                int row = wn + j * 16 + b_row;
                int ck = 2 * kh + b_sel;
                uint32_t off = swz(row, ck);
                LDSM4(Bfh[j], sb + 2 * ASZ + off);
                LDSM4(Bfl[j], sb + 2 * ASZ + BSZ + off);
            }
#pragma unroll
            for (int t = 0; t < TM; t++)
#pragma unroll
                for (int j = 0; j < 4; j++) {
                    MMA16816(acc[t][2*j],   Afh[t], Bfh[j][0], Bfh[j][1]);
                    MMA16816(acc[t][2*j],   Afh[t], Bfl[j][0], Bfl[j][1]);
                    MMA16816(acc[t][2*j],   Afl[t], Bfh[j][0], Bfh[j][1]);
                    MMA16816(acc[t][2*j+1], Afh[t], Bfh[j][2], Bfh[j][3]);
                    MMA16816(acc[t][2*j+1], Afh[t], Bfl[j][2], Bfl[j][3]);
                    MMA16816(acc[t][2*j+1], Afl[t], Bfh[j][2], Bfh[j][3]);
                }
        }
        __syncthreads();
    }
#undef ISSUE

    // epilogue
#pragma unroll
    for (int t = 0; t < TM; t++) {
        int r0 = bm + wm + t * 16 + (lane >> 2);
#pragma unroll
        for (int j = 0; j < 8; j++) {
            int col = bn + wn + j * 8 + (lane & 3) * 2;
            float v0 = acc[t][j][0] * alpha;
            float v1 = acc[t][j][1] * alpha;
            float v2 = acc[t][j][2] * alpha;
            float v3 = acc[t][j][3] * alpha;
            if (bias) { v0 += bias[col]; v1 += bias[col + 1]; v2 += bias[col]; v3 += bias[col + 1]; }
            if (D) {
                v0 += D[(long long)r0 * ldd + col];
                v1 += D[(long long)r0 * ldd + col + 1];
                v2 += D[(long long)(r0 + 8) * ldd + col];
                v3 += D[(long long)(r0 + 8) * ldd + col + 1];
            }
            if (Chi) {
                long long o0 = (long long)r0 * ldc + col;
                long long o1 = (long long)(r0 + 8) * ldc + col;
                split2x2(v0, v1, Chi + o0, Clo + o0);
                split2x2(v2, v3, Chi + o1, Clo + o1);
            } else {
                C[(long long)r0 * ldc + col]           = v0;
                C[(long long)r0 * ldc + col + 1]       = v1;
                C[(long long)(r0 + 8) * ldc + col]     = v2;
                C[(long long)(r0 + 8) * ldc + col + 1] = v3;
            }
        }
    }
}

// ---------------- conversions ----------------
__global__ void cvt_split_kernel(const float* __restrict__ s, bf16* __restrict__ hi, bf16* __restrict__ lo, long long n)
{
    long long i = (long long)blockIdx.x * blockDim.x + threadIdx.x;
    long long st = (long long)gridDim.x * blockDim.x;
    for (; i < n; i += st) split2(s[i], hi + i, lo + i);
}

// qab [h][c][d], oabT [h][d][c] from kv_b_W [c, h, 2, d]
__global__ void extract_kernel(const float* __restrict__ kvb,
                               bf16* __restrict__ qh, bf16* __restrict__ ql,
                               bf16* __restrict__ oh, bf16* __restrict__ ol)
{
    long long n = (long long)CNH * CKVLR * CHD;
    long long i = (long long)blockIdx.x * blockDim.x + threadIdx.x;
    long long st = (long long)gridDim.x * blockDim.x;
    for (; i < n; i += st) {
        {
            int c = (int)(i & 511);
            int d = (int)((i >> 9) & 127);
            int h = (int)(i >> 16);
            float v = kvb[(((long long)c * CNH + h) * 2 + 1) * CHD + d];
            split2(v, oh + i, ol + i);
        }
        {
            int d = (int)(i & 127);
            int c = (int)((i >> 7) & 511);
            int h = (int)(i >> 16);
            float v = kvb[(((long long)c * CNH + h) * 2) * CHD + d];
            split2(v, qh + i, ql + i);
        }
    }
}

// ckvT [b][c(512)][t(2048)] from ckv [b,t,640]
__global__ void cvt_ckvt_kernel(const float* __restrict__ ckv, bf16* __restrict__ hi, bf16* __restrict__ lo)
{
    long long n = (long long)CB * CKVLR * CS;
    long long i = (long long)blockIdx.x * blockDim.x + threadIdx.x;
    long long st = (long long)gridDim.x * blockDim.x;
    for (; i < n; i += st) {
        int t = (int)(i & 2047);
        int c = (int)((i >> 11) & 511);
        int b = (int)(i >> 20);
        float v = ckv[((long long)b * CS + t) * CCAT + c];
        split2(v, hi + i, lo + i);
    }
}

// ---------------- RMSNorm (read fp32, write split) ----------------
__global__ __launch_bounds__(256) void rms_kernel(const float* __restrict__ x, const float* __restrict__ w,
                                                  bf16* __restrict__ hi, bf16* __restrict__ lo)
{
    __shared__ float red[8];
    size_t row = blockIdx.x;
    const float* p = x + row * CQLR;
    int tid = threadIdx.x;
    float s = 0.f;
    for (int i = tid; i < CQLR; i += 256) { float v = p[i]; s += v * v; }
#pragma unroll
    for (int o = 16; o; o >>= 1) s += __shfl_xor_sync(~0u, s, o);
    if ((tid & 31) == 0) red[tid >> 5] = s;
    __syncthreads();
    float tot = 0.f;
#pragma unroll
    for (int i = 0; i < 8; i++) tot += red[i];
    float r = rsqrtf(tot + 1e-6f);
    bf16* ph = hi + row * CQLR;
    bf16* pl = lo + row * CQLR;
    for (int i = tid; i < CQLR; i += 256) split2(p[i] * r * w[i], ph + i, pl + i);
}

// ---------------- softmax + bf16 split ----------------
__global__ __launch_bounds__(256) void softmax_split_kernel(const float* __restrict__ x,
                                                            bf16* __restrict__ hi, bf16* __restrict__ lo)
{
    __shared__ float red[8];
    size_t row = blockIdx.x;
    const float* p = x + row * (size_t)CS;
    int tid = threadIdx.x;
    float vmax = -1e30f;
    for (int i = tid; i < CS; i += 256) vmax = fmaxf(vmax, p[i]);
#pragma unroll
    for (int o = 16; o; o >>= 1) vmax = fmaxf(vmax, __shfl_xor_sync(~0u, vmax, o));
    if ((tid & 31) == 0) red[tid >> 5] = vmax;
    __syncthreads();
    float m = -1e30f;
#pragma unroll
    for (int i = 0; i < 8; i++) m = fmaxf(m, red[i]);
    __syncthreads();
    float s = 0.f;
    for (int i = tid; i < CS; i += 256) s += __expf(p[i] - m);
#pragma unroll
    for (int o = 16; o; o >>= 1) s += __shfl_xor_sync(~0u, s, o);
    if ((tid & 31) == 0) red[tid >> 5] = s;
    __syncthreads();
    float tot = 0.f;
#pragma unroll
    for (int i = 0; i < 8; i++) tot += red[i];
    float inv = 1.f / tot;
    bf16* ph = hi + row * (size_t)CS;
    bf16* pl = lo + row * (size_t)CS;
    for (int i = tid; i < CS; i += 256) {
        float e = __expf(p[i] - m) * inv;
        split2(e, ph + i, pl + i);
    }
}

// ---------------- RoPE ----------------
__device__ __forceinline__ void rope_cs(int s, int i, float& c, float& sn)
{
    double invf = pow(10000.0, -(double)(2 * i) / 128.0);
    double ang = (double)s * invf;
    c = (float)cos(ang);
    sn = (float)sin(ang);
}

__global__ void rope_k_kernel(float* __restrict__ ckv)
{
    int idx = blockIdx.x * blockDim.x + threadIdx.x;
    if (idx >= CB * CS * 64) return;
    int i = idx & 63;
    int row = idx >> 6;
    int s = row & (CS - 1);
    float c, sn; rope_cs(s, i, c, sn);
    float* p = ckv + (size_t)row * CCAT + CKVLR;
    float x1 = p[i], x2 = p[i + 64];
    p[i]      = x1 * c - x2 * sn;
    p[i + 64] = x2 * c + x1 * sn;
}

// q_pe: read split q [b,s,h,256] cols 128..255, rope, write split into qcat [b,h,s,640] cols 512..639
__global__ void rope_q_kernel(const bf16* __restrict__ qh, const bf16* __restrict__ ql,
                              bf16* __restrict__ qch, bf16* __restrict__ qcl)
{
    int idx = blockIdx.x * blockDim.x + threadIdx.x;
    if (idx >= CB * CS * CNH * 64) return;
    int i = idx & 63;
    int h = (idx >> 6) & 15;
    int row = idx >> 10;
    int s = row & (CS - 1);
    int b = row >> 11;
    float c, sn; rope_cs(s, i, c, sn);
    long long so = (long long)row * (CNH * CQHD) + h * CQHD + CHD;
    float x1 = __bfloat162float(qh[so + i])      + __bfloat162float(ql[so + i]);
    float x2 = __bfloat162float(qh[so + i + 64]) + __bfloat162float(ql[so + i + 64]);
    long long dofs = ((long long)(b * CNH + h) * CS + s) * CCAT + CKVLR;
    split2(x1 * c - x2 * sn, qch + dofs + i,      qcl + dofs + i);
    split2(x2 * c + x1 * sn, qch + dofs + i + 64, qcl + dofs + i + 64);
}

// ---------------- launch ----------------
extern "C" void kernel_launch(void* const* d_in, const int* in_sizes, int n_in,
                              void* d_out, int out_size)
{
    const float* hidden = (const float*)d_in[0];
    const float* mask   = (const float*)d_in[1];
    const float* q_a_W  = (const float*)d_in[2];
    const float* q_a_b  = (const float*)d_in[3];
    const float* q_a_nw = (const float*)d_in[4];
    const float* q_b_W  = (const float*)d_in[5];
    const float* kv_a_W = (const float*)d_in[6];
    const float* kv_b_W = (const float*)d_in[7];
    const float* o_W    = (const float*)d_in[8];
    float* out = (float*)d_out;

    void* p;
#define SYM(v, g) cudaGetSymbolAddress(&p, g); auto* v = (decltype(&g[0]))p
    SYM(qa, g_qa);     SYM(ckv, g_ckv);   SYM(sc, g_scores);
    SYM(hidh, g_hid_h); SYM(hidl, g_hid_l);
    SYM(qawh, g_qaw_h); SYM(qawl, g_qaw_l);
    SYM(qbwh, g_qbw_h); SYM(qbwl, g_qbw_l);
    SYM(kvawh, g_kvaw_h); SYM(kvawl, g_kvaw_l);
    SYM(owh, g_ow_h);   SYM(owl, g_ow_l);
    SYM(qanh, g_qan_h); SYM(qanl, g_qan_l);
    SYM(qsh, g_qs_h);   SYM(qsl, g_qs_l);
    SYM(qabh, g_qab_h); SYM(qabl, g_qab_l);
    SYM(oabth, g_oabt_h); SYM(oabtl, g_oabt_l);
    SYM(qch, g_qc_h);   SYM(qcl, g_qc_l);
    SYM(ckvh, g_ckv_h); SYM(ckvl, g_ckv_l);
    SYM(ckvth, g_ckvt_h); SYM(ckvtl, g_ckvt_l);
    SYM(atth, g_att_h); SYM(attl, g_att_l);
    SYM(olh, g_ol_h);   SYM(oll, g_ol_l);
    SYM(ohh, g_oh_h);   SYM(ohl, g_oh_l);
#undef SYM

    constexpr int SMEM128 = STAGES * (2 * ASZ + 2 * 128 * GBK * 2);  // 128 KB
    constexpr int SMEM256 = STAGES * (2 * ASZ + 2 * 256 * GBK * 2);  // 192 KB
    cudaFuncSetAttribute(mma_gemm<128>, cudaFuncAttributeMaxDynamicSharedMemorySize, SMEM128);
    cudaFuncSetAttribute(mma_gemm<256>, cudaFuncAttributeMaxDynamicSharedMemorySize, SMEM256);

    const long long LS = CS;
    const int CVG = 2048;

    cvt_split_kernel<<<CVG, 256>>>(hidden, hidh, hidl, (long long)CBS * CHID);
    cvt_split_kernel<<<CVG, 256>>>(q_a_W, qawh, qawl, (long long)CQLR * CHID);
    cvt_split_kernel<<<CVG, 256>>>(q_b_W, qbwh, qbwl, (long long)CNH * CQHD * CQLR);
    cvt_split_kernel<<<CVG, 256>>>(o_W, owh, owl, (long long)CHID * CNH * CHD);
    cvt_split_kernel<<<CVG, 256>>>(kv_a_W, kvawh, kvawl, (long long)CCAT * CHID);
    extract_kernel<<<CVG, 256>>>(kv_b_W, qabh, qabl, oabth, oabtl);

    // 1) q_a = hidden @ q_a_W^T + bias   [4096,1536] K=2048, fp32 out
    mma_gemm<256><<<dim3(CQLR / 256, CBS / 128, 1), 256, SMEM256>>>(
        hidh, hidl, CHID, 0, 0, qawh, qawl, CHID, 0, 0,
        qa, nullptr, nullptr, CQLR, 0, 0, nullptr, 0, 0, 0, q_a_b, 1.f, CHID, 1);

    // 2) rmsnorm -> split
    rms_kernel<<<CBS, 256>>>(qa, q_a_nw, qanh, qanl);

    // 3) q = qa_norm @ q_b_W^T  [4096,4096] K=1536, split out
    mma_gemm<256><<<dim3((CNH * CQHD) / 256, CBS / 128, 1), 256, SMEM256>>>(
        qanh, qanl, CQLR, 0, 0, qbwh, qbwl, CQLR, 0, 0,
        nullptr, qsh, qsl, CNH * CQHD, 0, 0, nullptr, 0, 0, 0, nullptr, 1.f, CQLR, 1);

    // 4) ckv = hidden @ kv_a_W^T  [4096,640] K=2048, fp32 out
    mma_gemm<128><<<dim3(CCAT / 128, CBS / 128, 1), 256, SMEM128>>>(
        hidh, hidl, CHID, 0, 0, kvawh, kvawl, CHID, 0, 0,
        ckv, nullptr, nullptr, CCAT, 0, 0, nullptr, 0, 0, 0, nullptr, 1.f, CHID, 1);

    // 5) RoPE
    rope_k_kernel<<<(CB * CS * 64) / 256, 256>>>(ckv);
    rope_q_kernel<<<(CB * CS * CNH * 64) / 256, 256>>>(qsh, qsl, qch, qcl);

    // 6) q_lat -> qcat cols [0,512)  K=128, Z=32, split out
    mma_gemm<256><<<dim3(CKVLR / 256, CS / 128, CB * CNH), 256, SMEM256>>>(
        qsh, qsl, CNH * CQHD, LS * CNH * CQHD, CQHD,
        qabh, qabl, CHD, 0, (long long)CKVLR * CHD,
        nullptr, qch, qcl, CCAT, LS * CNH * CCAT, LS * CCAT,
        nullptr, 0, 0, 0, nullptr, 1.f, CHD, CNH);

    // 7) splits of ckv
    cvt_split_kernel<<<CVG, 256>>>(ckv, ckvh, ckvl, (long long)CBS * CCAT);
    cvt_ckvt_kernel<<<CVG, 256>>>(ckv, ckvth, ckvtl);

    // 8) scores = (qcat . ckv^T)*scale + mask  K=640, Z=32, fp32 out
    float scale = 1.f / sqrtf((float)CCAT);
    mma_gemm<256><<<dim3(CS / 256, CS / 128, CB * CNH), 256, SMEM256>>>(
        qch, qcl, CCAT, LS * CNH * CCAT, LS * CCAT,
        ckvh, ckvl, CCAT, LS * CCAT, 0,
        sc, nullptr, nullptr, CS, LS * CNH * CS, LS * CS,
        mask, CS, LS * CS, 0, nullptr, scale, CCAT, CNH);

    // 9) softmax -> split
    softmax_split_kernel<<<CB * CNH * CS, 256>>>(sc, atth, attl);

    // 10) out_lat = attn @ ckv[:, :512]  K=2048, Z=32 (ckvT), split out
    mma_gemm<256><<<dim3(CKVLR / 256, CS / 128, CB * CNH), 256, SMEM256>>>(
        atth, attl, CS, LS * CNH * CS, LS * CS,
        ckvth, ckvtl, CS, (long long)CKVLR * CS, 0,
        nullptr, olh, oll, CKVLR, LS * CNH * CKVLR, LS * CKVLR,
        nullptr, 0, 0, 0, nullptr, 1.f, CS, CNH);

    // 11) out_head = olat . o_absorb^T -> [b,s,h*128+d]  K=512, N=128, Z=32, split out
    mma_gemm<128><<<dim3(1, CS / 128, CB * CNH), 256, SMEM128>>>(
        olh, oll, CKVLR, LS * CNH * CKVLR, LS * CKVLR,
        oabth, oabtl, CKVLR, 0, (long long)CHD * CKVLR,
        nullptr, ohh, ohl, CNH * CHD, LS * (long long)CNH * CHD, CHD,
        nullptr, 0, 0, 0, nullptr, 1.f, CKVLR, CNH);

    // 12) final = ohead @ o_W^T  [4096,2048] K=2048, fp32 out
    mma_gemm<256><<<dim3(CHID / 256, CBS / 128, 1), 256, SMEM256>>>(
        ohh, ohl, CNH * CHD, 0, 0, owh, owl, CNH * CHD, 0, 0,
        out, nullptr, nullptr, CHID, 0, 0, nullptr, 0, 0, 0, nullptr, 1.f, CNH * CHD, 1);
}

// round 5
// speedup vs baseline: 2.5450x; 1.0651x over previous
#include <cuda_runtime.h>
#include <cuda_bf16.h>
#include <math.h>
#include <stdint.h>

// ---------------- problem constants ----------------
#define CB   2
#define CS   2048
#define CHID 2048
#define CNH  16
#define CHD  128
#define CQLR 1536
#define CKVLR 512
#define CBS  (CB*CS)          // 4096
#define CCAT (CKVLR+CHD)      // 640
#define CQHD (2*CHD)          // 256

typedef __nv_bfloat16 bf16;

// ---------------- device scratch ----------------
static __device__ __align__(256) float g_qa[(size_t)CBS*CQLR];
static __device__ __align__(256) float g_ckv[(size_t)CBS*CCAT];
static __device__ __align__(256) float g_scores[(size_t)CB*CNH*CS*CS];

static __device__ __align__(256) bf16 g_hid_h[(size_t)CBS*CHID],  g_hid_l[(size_t)CBS*CHID];
static __device__ __align__(256) bf16 g_qaw_h[(size_t)CQLR*CHID], g_qaw_l[(size_t)CQLR*CHID];
static __device__ __align__(256) bf16 g_qbw_h[(size_t)CNH*CQHD*CQLR], g_qbw_l[(size_t)CNH*CQHD*CQLR];
static __device__ __align__(256) bf16 g_kvaw_h[(size_t)CCAT*CHID], g_kvaw_l[(size_t)CCAT*CHID];
static __device__ __align__(256) bf16 g_ow_h[(size_t)CHID*CNH*CHD], g_ow_l[(size_t)CHID*CNH*CHD];
static __device__ __align__(256) bf16 g_qan_h[(size_t)CBS*CQLR], g_qan_l[(size_t)CBS*CQLR];
static __device__ __align__(256) bf16 g_qs_h[(size_t)CBS*CNH*CQHD], g_qs_l[(size_t)CBS*CNH*CQHD];
static __device__ __align__(256) bf16 g_qab_h[(size_t)CNH*CKVLR*CHD], g_qab_l[(size_t)CNH*CKVLR*CHD];     // [h][c][d]
static __device__ __align__(256) bf16 g_oabt_h[(size_t)CNH*CHD*CKVLR], g_oabt_l[(size_t)CNH*CHD*CKVLR];   // [h][d][c]
static __device__ __align__(256) bf16 g_qc_h[(size_t)CB*CNH*CS*CCAT], g_qc_l[(size_t)CB*CNH*CS*CCAT];
static __device__ __align__(256) bf16 g_ckv_h[(size_t)CBS*CCAT], g_ckv_l[(size_t)CBS*CCAT];
static __device__ __align__(256) bf16 g_ckvt_h[(size_t)CB*CKVLR*CS], g_ckvt_l[(size_t)CB*CKVLR*CS];       // [b][c][t]
static __device__ __align__(256) bf16 g_att_h[(size_t)CB*CNH*CS*CS], g_att_l[(size_t)CB*CNH*CS*CS];
static __device__ __align__(256) bf16 g_ol_h[(size_t)CB*CNH*CS*CKVLR], g_ol_l[(size_t)CB*CNH*CS*CKVLR];
static __device__ __align__(256) bf16 g_oh_h[(size_t)CBS*CNH*CHD], g_oh_l[(size_t)CBS*CNH*CHD];

// ---------------- asm helpers (sm_80-portable) ----------------
__device__ __forceinline__ uint32_t smem_u32(const void* p) {
    uint32_t a;
    asm("{ .reg .u64 t; cvta.to.shared.u64 t, %1; cvt.u32.u64 %0, t; }" : "=r"(a) : "l"(p));
    return a;
}
#define CP_ASYNC16(dst, src) \
    asm volatile("cp.async.cg.shared.global [%0], [%1], 16;" :: "r"(dst), "l"(src) : "memory")
#define CP_COMMIT() asm volatile("cp.async.commit_group;" ::: "memory")
#define CP_WAIT(n)  asm volatile("cp.async.wait_group %0;" :: "n"(n) : "memory")

#define LDSM4(r, addr) \
    asm volatile("ldmatrix.sync.aligned.m8n8.x4.shared.b16 {%0,%1,%2,%3}, [%4];" \
        : "=r"((r)[0]),"=r"((r)[1]),"=r"((r)[2]),"=r"((r)[3]) : "r"(addr))

#define MMA16816(d, a, b0, b1) \
    asm volatile("mma.sync.aligned.m16n8k16.row.col.f32.bf16.bf16.f32 " \
        "{%0,%1,%2,%3},{%4,%5,%6,%7},{%8,%9},{%0,%1,%2,%3};" \
        : "+f"((d)[0]),"+f"((d)[1]),"+f"((d)[2]),"+f"((d)[3]) \
        : "r"((a)[0]),"r"((a)[1]),"r"((a)[2]),"r"((a)[3]), "r"(b0),"r"(b1))

__device__ __forceinline__ void split2(float v, bf16* hp, bf16* lp) {
    bf16 h = __float2bfloat16(v);
    *hp = h;
    *lp = __float2bfloat16(v - __bfloat162float(h));
}
__device__ __forceinline__ void split2x2(float v0, float v1, bf16* hp, bf16* lp) {
    bf16 h0 = __float2bfloat16(v0), h1 = __float2bfloat16(v1);
    bf16 l0 = __float2bfloat16(v0 - __bfloat162float(h0));
    bf16 l1 = __float2bfloat16(v1 - __bfloat162float(h1));
    __nv_bfloat162 hh; hh.x = h0; hh.y = h1;
    __nv_bfloat162 ll; ll.x = l0; ll.y = l1;
    *reinterpret_cast<__nv_bfloat162*>(hp) = hh;
    *reinterpret_cast<__nv_bfloat162*>(lp) = ll;
}

// ---------------- bf16 hi/lo split MMA GEMM ----------------
// C[m,n] = alpha*sum_k A[m,k]*B[n,k] (+bias[n]) (+D[m,n]); A,B bf16 hi/lo, K-major.
// BN=128: 8 warps 4mx2n, warp 32x64.   BN=256: 8 warps 2mx4n, warp 64x64.
static constexpr int GBK = 32, STAGES = 4;
static constexpr int ASZ = 128 * GBK * 2;   // 8192 B

__device__ __forceinline__ uint32_t swz(int row, int ch) {
    return (uint32_t)(row * 64 + ((ch ^ ((row >> 1) & 3)) * 16));
}

template<int BN>
__global__ __launch_bounds__(256, 1) void mma_gemm(
    const bf16* __restrict__ Ah, const bf16* __restrict__ Al, int lda, long long aO, long long aI,
    const bf16* __restrict__ Bh, const bf16* __restrict__ Bl, int ldb, long long bO, long long bI,
    float* __restrict__ C, bf16* __restrict__ Chi, bf16* __restrict__ Clo,
    int ldc, long long cO, long long cI,
    const float* __restrict__ D, int ldd, long long dO, long long dI,
    const float* __restrict__ bias, float alpha, int K, int zInner)
{
    constexpr int TM = (BN == 256) ? 4 : 2;
    constexpr int BSZ = BN * GBK * 2;
    constexpr int BCH = BN * 4;               // 16B chunks per B sub-tile
    constexpr int STAGE_B = 2 * ASZ + 2 * BSZ;

    extern __shared__ char smem_raw[];
    uint32_t sbase = smem_u32(smem_raw);

    int tid = threadIdx.x, wid = tid >> 5, lane = tid & 31;
    int z = blockIdx.z, zo = z / zInner, zi = z - zo * zInner;
    Ah += zo * aO + zi * aI;  Al += zo * aO + zi * aI;
    Bh += zo * bO + zi * bI;  Bl += zo * bO + zi * bI;
    if (C)   C   += zo * cO + zi * cI;
    if (Chi) { Chi += zo * cO + zi * cI; Clo += zo * cO + zi * cI; }
    if (D) D += zo * dO + zi * dI;

    int bm = blockIdx.y * 128, bn = blockIdx.x * BN;
    int wm, wn;
    if (BN == 256) { wm = (wid & 1) * 64; wn = (wid >> 1) * 64; }
    else           { wm = (wid & 3) * 32; wn = (wid >> 2) * 64; }

    const bf16* pAh = Ah + (long long)bm * lda;
    const bf16* pAl = Al + (long long)bm * lda;
    const bf16* pBh = Bh + (long long)bn * ldb;
    const bf16* pBl = Bl + (long long)bn * ldb;

    float acc[TM][8][4];
#pragma unroll
    for (int t = 0; t < TM; t++)
#pragma unroll
        for (int j = 0; j < 8; j++)
#pragma unroll
            for (int q = 0; q < 4; q++) acc[t][j][q] = 0.f;

    int nk = K / GBK;

#define ISSUE(stage_) do { \
    int st_ = (stage_) % STAGES; \
    uint32_t sb_ = sbase + st_ * STAGE_B; \
    long long k0_ = (long long)(stage_) * GBK; \
    _Pragma("unroll") \
    for (int u = 0; u < 2; u++) { \
        int idx = u * 256 + tid; int r = idx >> 2, ch = idx & 3; \
        uint32_t so = swz(r, ch); \
        CP_ASYNC16(sb_ + so,       pAh + (long long)r * lda + k0_ + ch * 8); \
        CP_ASYNC16(sb_ + ASZ + so, pAl + (long long)r * lda + k0_ + ch * 8); \
    } \
    _Pragma("unroll") \
    for (int u = 0; u < BCH / 256; u++) { \
        int idx = u * 256 + tid; int r = idx >> 2, ch = idx & 3; \
        uint32_t so = swz(r, ch); \
        CP_ASYNC16(sb_ + 2 * ASZ + so,       pBh + (long long)r * ldb + k0_ + ch * 8); \
        CP_ASYNC16(sb_ + 2 * ASZ + BSZ + so, pBl + (long long)r * ldb + k0_ + ch * 8); \
    } \
} while (0)

    for (int s = 0; s < STAGES - 1; s++) {
        if (s < nk) ISSUE(s);
        CP_COMMIT();
    }

    int a_row = (lane & 15);
    int a_sel = lane >> 4;
    int b_g   = lane >> 3;
    int b_row = (lane & 7) + ((b_g >> 1) * 8);
    int b_sel = b_g & 1;

    for (int i = 0; i < nk; i++) {
        CP_WAIT(STAGES - 2);   // group i complete -> stage i%STAGES ready
        __syncthreads();       // all warps see stage i; all done reading stage (i-1)%STAGES
        if (i + STAGES - 1 < nk) ISSUE(i + STAGES - 1);  // overwrites stage (i-1)%STAGES
        CP_COMMIT();

        uint32_t sb = sbase + (i % STAGES) * STAGE_B;

#pragma unroll
        for (int kh = 0; kh < 2; kh++) {
            uint32_t Afh[TM][4], Afl[TM][4];
#pragma unroll
            for (int t = 0; t < TM; t++) {
                int row = wm + t * 16 + a_row;
                int ck = 2 * kh + a_sel;
                uint32_t off = swz(row, ck);
                LDSM4(Afh[t], sb + off);
                LDSM4(Afl[t], sb + ASZ + off);
            }
            uint32_t Bfh[4][4], Bfl[4][4];
#pragma unroll
            for (int j = 0; j < 4; j++) {
                int row = wn + j * 16 + b_row;
                int ck = 2 * kh + b_sel;
                uint32_t off = swz(row, ck);
                LDSM4(Bfh[j], sb + 2 * ASZ + off);
                LDSM4(Bfl[j], sb + 2 * ASZ + BSZ + off);
            }
#pragma unroll
            for (int t = 0; t < TM; t++)
#pragma unroll
                for (int j = 0; j < 4; j++) {
                    MMA16816(acc[t][2*j],   Afh[t], Bfh[j][0], Bfh[j][1]);
                    MMA16816(acc[t][2*j],   Afh[t], Bfl[j][0], Bfl[j][1]);
                    MMA16816(acc[t][2*j],   Afl[t], Bfh[j][0], Bfh[j][1]);
                    MMA16816(acc[t][2*j+1], Afh[t], Bfh[j][2], Bfh[j][3]);
                    MMA16816(acc[t][2*j+1], Afh[t], Bfl[j][2], Bfl[j][3]);
                    MMA16816(acc[t][2*j+1], Afl[t], Bfh[j][2], Bfh[j][3]);
                }
        }
    }
#undef ISSUE

    // epilogue
#pragma unroll
    for (int t = 0; t < TM; t++) {
        int r0 = bm + wm + t * 16 + (lane >> 2);
#pragma unroll
        for (int j = 0; j < 8; j++) {
            int col = bn + wn + j * 8 + (lane & 3) * 2;
            float v0 = acc[t][j][0] * alpha;
            float v1 = acc[t][j][1] * alpha;
            float v2 = acc[t][j][2] * alpha;
            float v3 = acc[t][j][3] * alpha;
            if (bias) { v0 += bias[col]; v1 += bias[col + 1]; v2 += bias[col]; v3 += bias[col + 1]; }
            if (D) {
                v0 += D[(long long)r0 * ldd + col];
                v1 += D[(long long)r0 * ldd + col + 1];
                v2 += D[(long long)(r0 + 8) * ldd + col];
                v3 += D[(long long)(r0 + 8) * ldd + col + 1];
            }
            if (Chi) {
                long long o0 = (long long)r0 * ldc + col;
                long long o1 = (long long)(r0 + 8) * ldc + col;
                split2x2(v0, v1, Chi + o0, Clo + o0);
                split2x2(v2, v3, Chi + o1, Clo + o1);
            } else {
                C[(long long)r0 * ldc + col]           = v0;
                C[(long long)r0 * ldc + col + 1]       = v1;
                C[(long long)(r0 + 8) * ldc + col]     = v2;
                C[(long long)(r0 + 8) * ldc + col + 1] = v3;
            }
        }
    }
}

// ---------------- conversions ----------------
__global__ void cvt_split_kernel(const float* __restrict__ s, bf16* __restrict__ hi, bf16* __restrict__ lo, long long n)
{
    long long i = (long long)blockIdx.x * blockDim.x + threadIdx.x;
    long long st = (long long)gridDim.x * blockDim.x;
    for (; i < n; i += st) split2(s[i], hi + i, lo + i);
}

// qab [h][c][d], oabT [h][d][c] from kv_b_W [c, h, 2, d]
__global__ void extract_kernel(const float* __restrict__ kvb,
                               bf16* __restrict__ qh, bf16* __restrict__ ql,
                               bf16* __restrict__ oh, bf16* __restrict__ ol)
{
    long long n = (long long)CNH * CKVLR * CHD;
    long long i = (long long)blockIdx.x * blockDim.x + threadIdx.x;
    long long st = (long long)gridDim.x * blockDim.x;
    for (; i < n; i += st) {
        {
            int c = (int)(i & 511);
            int d = (int)((i >> 9) & 127);
            int h = (int)(i >> 16);
            float v = kvb[(((long long)c * CNH + h) * 2 + 1) * CHD + d];
            split2(v, oh + i, ol + i);
        }
        {
            int d = (int)(i & 127);
            int c = (int)((i >> 7) & 511);
            int h = (int)(i >> 16);
            float v = kvb[(((long long)c * CNH + h) * 2) * CHD + d];
            split2(v, qh + i, ql + i);
        }
    }
}

// ckvT [b][c(512)][t(2048)] from ckv [b,t,640]
__global__ void cvt_ckvt_kernel(const float* __restrict__ ckv, bf16* __restrict__ hi, bf16* __restrict__ lo)
{
    long long n = (long long)CB * CKVLR * CS;
    long long i = (long long)blockIdx.x * blockDim.x + threadIdx.x;
    long long st = (long long)gridDim.x * blockDim.x;
    for (; i < n; i += st) {
        int t = (int)(i & 2047);
        int c = (int)((i >> 11) & 511);
        int b = (int)(i >> 20);
        float v = ckv[((long long)b * CS + t) * CCAT + c];
        split2(v, hi + i, lo + i);
    }
}

// ---------------- RMSNorm (read fp32, write split) ----------------
__global__ __launch_bounds__(256) void rms_kernel(const float* __restrict__ x, const float* __restrict__ w,
                                                  bf16* __restrict__ hi, bf16* __restrict__ lo)
{
    __shared__ float red[8];
    size_t row = blockIdx.x;
    const float* p = x + row * CQLR;
    int tid = threadIdx.x;
    float s = 0.f;
    for (int i = tid; i < CQLR; i += 256) { float v = p[i]; s += v * v; }
#pragma unroll
    for (int o = 16; o; o >>= 1) s += __shfl_xor_sync(~0u, s, o);
    if ((tid & 31) == 0) red[tid >> 5] = s;
    __syncthreads();
    float tot = 0.f;
#pragma unroll
    for (int i = 0; i < 8; i++) tot += red[i];
    float r = rsqrtf(tot + 1e-6f);
    bf16* ph = hi + row * CQLR;
    bf16* pl = lo + row * CQLR;
    for (int i = tid; i < CQLR; i += 256) split2(p[i] * r * w[i], ph + i, pl + i);
}

// ---------------- softmax + bf16 split (single DRAM read, row in registers) ----------------
__global__ __launch_bounds__(256) void softmax_split_kernel(const float* __restrict__ x,
                                                            bf16* __restrict__ hi, bf16* __restrict__ lo)
{
    __shared__ float red[8];
    size_t row = blockIdx.x;
    const float4* p = reinterpret_cast<const float4*>(x + row * (size_t)CS);
    int tid = threadIdx.x;

    float4 a = p[tid];          // cols 4*tid   .. 4*tid+3
    float4 b = p[tid + 256];    // cols 4*tid+1024 ..

    float m = fmaxf(fmaxf(fmaxf(a.x, a.y), fmaxf(a.z, a.w)),
                    fmaxf(fmaxf(b.x, b.y), fmaxf(b.z, b.w)));
#pragma unroll
    for (int o = 16; o; o >>= 1) m = fmaxf(m, __shfl_xor_sync(~0u, m, o));
    if ((tid & 31) == 0) red[tid >> 5] = m;
    __syncthreads();
    m = fmaxf(fmaxf(fmaxf(red[0], red[1]), fmaxf(red[2], red[3])),
              fmaxf(fmaxf(red[4], red[5]), fmaxf(red[6], red[7])));
    __syncthreads();   // protect red[] reuse

    float e[8];
    e[0] = __expf(a.x - m); e[1] = __expf(a.y - m); e[2] = __expf(a.z - m); e[3] = __expf(a.w - m);
    e[4] = __expf(b.x - m); e[5] = __expf(b.y - m); e[6] = __expf(b.z - m); e[7] = __expf(b.w - m);
    float s = e[0] + e[1] + e[2] + e[3] + e[4] + e[5] + e[6] + e[7];
#pragma unroll
    for (int o = 16; o; o >>= 1) s += __shfl_xor_sync(~0u, s, o);
    if ((tid & 31) == 0) red[tid >> 5] = s;
    __syncthreads();
    float tot = red[0] + red[1] + red[2] + red[3] + red[4] + red[5] + red[6] + red[7];
    float inv = 1.f / tot;

    bf16* ph = hi + row * (size_t)CS;
    bf16* pl = lo + row * (size_t)CS;
    int c0 = 4 * tid, c1 = 4 * (tid + 256);
    split2x2(e[0] * inv, e[1] * inv, ph + c0,     pl + c0);
    split2x2(e[2] * inv, e[3] * inv, ph + c0 + 2, pl + c0 + 2);
    split2x2(e[4] * inv, e[5] * inv, ph + c1,     pl + c1);
    split2x2(e[6] * inv, e[7] * inv, ph + c1 + 2, pl + c1 + 2);
}

// ---------------- RoPE ----------------
__device__ __forceinline__ void rope_cs(int s, int i, float& c, float& sn)
{
    double invf = pow(10000.0, -(double)(2 * i) / 128.0);
    double ang = (double)s * invf;
    c = (float)cos(ang);
    sn = (float)sin(ang);
}

__global__ void rope_k_kernel(float* __restrict__ ckv)
{
    int idx = blockIdx.x * blockDim.x + threadIdx.x;
    if (idx >= CB * CS * 64) return;
    int i = idx & 63;
    int row = idx >> 6;
    int s = row & (CS - 1);
    float c, sn; rope_cs(s, i, c, sn);
    float* p = ckv + (size_t)row * CCAT + CKVLR;
    float x1 = p[i], x2 = p[i + 64];
    p[i]      = x1 * c - x2 * sn;
    p[i + 64] = x2 * c + x1 * sn;
}

// q_pe: read split q [b,s,h,256] cols 128..255, rope, write split into qcat [b,h,s,640] cols 512..639
__global__ void rope_q_kernel(const bf16* __restrict__ qh, const bf16* __restrict__ ql,
                              bf16* __restrict__ qch, bf16* __restrict__ qcl)
{
    int idx = blockIdx.x * blockDim.x + threadIdx.x;
    if (idx >= CB * CS * CNH * 64) return;
    int i = idx & 63;
    int h = (idx >> 6) & 15;
    int row = idx >> 10;
    int s = row & (CS - 1);
    int b = row >> 11;
    float c, sn; rope_cs(s, i, c, sn);
    long long so = (long long)row * (CNH * CQHD) + h * CQHD + CHD;
    float x1 = __bfloat162float(qh[so + i])      + __bfloat162float(ql[so + i]);
    float x2 = __bfloat162float(qh[so + i + 64]) + __bfloat162float(ql[so + i + 64]);
    long long dofs = ((long long)(b * CNH + h) * CS + s) * CCAT + CKVLR;
    split2(x1 * c - x2 * sn, qch + dofs + i,      qcl + dofs + i);
    split2(x2 * c + x1 * sn, qch + dofs + i + 64, qcl + dofs + i + 64);
}

// ---------------- launch ----------------
extern "C" void kernel_launch(void* const* d_in, const int* in_sizes, int n_in,
                              void* d_out, int out_size)
{
    const float* hidden = (const float*)d_in[0];
    const float* mask   = (const float*)d_in[1];
    const float* q_a_W  = (const float*)d_in[2];
    const float* q_a_b  = (const float*)d_in[3];
    const float* q_a_nw = (const float*)d_in[4];
    const float* q_b_W  = (const float*)d_in[5];
    const float* kv_a_W = (const float*)d_in[6];
    const float* kv_b_W = (const float*)d_in[7];
    const float* o_W    = (const float*)d_in[8];
    float* out = (float*)d_out;

    void* p;
#define SYM(v, g) cudaGetSymbolAddress(&p, g); auto* v = (decltype(&g[0]))p
    SYM(qa, g_qa);     SYM(ckv, g_ckv);   SYM(sc, g_scores);
    SYM(hidh, g_hid_h); SYM(hidl, g_hid_l);
    SYM(qawh, g_qaw_h); SYM(qawl, g_qaw_l);
    SYM(qbwh, g_qbw_h); SYM(qbwl, g_qbw_l);
    SYM(kvawh, g_kvaw_h); SYM(kvawl, g_kvaw_l);
    SYM(owh, g_ow_h);   SYM(owl, g_ow_l);
    SYM(qanh, g_qan_h); SYM(qanl, g_qan_l);
    SYM(qsh, g_qs_h);   SYM(qsl, g_qs_l);
    SYM(qabh, g_qab_h); SYM(qabl, g_qab_l);
    SYM(oabth, g_oabt_h); SYM(oabtl, g_oabt_l);
    SYM(qch, g_qc_h);   SYM(qcl, g_qc_l);
    SYM(ckvh, g_ckv_h); SYM(ckvl, g_ckv_l);
    SYM(ckvth, g_ckvt_h); SYM(ckvtl, g_ckvt_l);
    SYM(atth, g_att_h); SYM(attl, g_att_l);
    SYM(olh, g_ol_h);   SYM(oll, g_ol_l);
    SYM(ohh, g_oh_h);   SYM(ohl, g_oh_l);
#undef SYM

    constexpr int SMEM128 = STAGES * (2 * ASZ + 2 * 128 * GBK * 2);  // 128 KB
    constexpr int SMEM256 = STAGES * (2 * ASZ + 2 * 256 * GBK * 2);  // 192 KB
    cudaFuncSetAttribute(mma_gemm<128>, cudaFuncAttributeMaxDynamicSharedMemorySize, SMEM128);
    cudaFuncSetAttribute(mma_gemm<256>, cudaFuncAttributeMaxDynamicSharedMemorySize, SMEM256);

    const long long LS = CS;
    const int CVG = 2048;

    cvt_split_kernel<<<CVG, 256>>>(hidden, hidh, hidl, (long long)CBS * CHID);
    cvt_split_kernel<<<CVG, 256>>>(q_a_W, qawh, qawl, (long long)CQLR * CHID);
    cvt_split_kernel<<<CVG, 256>>>(q_b_W, qbwh, qbwl, (long long)CNH * CQHD * CQLR);
    cvt_split_kernel<<<CVG, 256>>>(o_W, owh, owl, (long long)CHID * CNH * CHD);
    cvt_split_kernel<<<CVG, 256>>>(kv_a_W, kvawh, kvawl, (long long)CCAT * CHID);
    extract_kernel<<<CVG, 256>>>(kv_b_W, qabh, qabl, oabth, oabtl);

    // 1) q_a = hidden @ q_a_W^T + bias   [4096,1536] K=2048, fp32 out
    mma_gemm<256><<<dim3(CQLR / 256, CBS / 128, 1), 256, SMEM256>>>(
        hidh, hidl, CHID, 0, 0, qawh, qawl, CHID, 0, 0,
        qa, nullptr, nullptr, CQLR, 0, 0, nullptr, 0, 0, 0, q_a_b, 1.f, CHID, 1);

    // 2) rmsnorm -> split
    rms_kernel<<<CBS, 256>>>(qa, q_a_nw, qanh, qanl);

    // 3) q = qa_norm @ q_b_W^T  [4096,4096] K=1536, split out
    mma_gemm<256><<<dim3((CNH * CQHD) / 256, CBS / 128, 1), 256, SMEM256>>>(
        qanh, qanl, CQLR, 0, 0, qbwh, qbwl, CQLR, 0, 0,
        nullptr, qsh, qsl, CNH * CQHD, 0, 0, nullptr, 0, 0, 0, nullptr, 1.f, CQLR, 1);

    // 4) ckv = hidden @ kv_a_W^T  [4096,640] K=2048, fp32 out
    mma_gemm<128><<<dim3(CCAT / 128, CBS / 128, 1), 256, SMEM128>>>(
        hidh, hidl, CHID, 0, 0, kvawh, kvawl, CHID, 0, 0,
        ckv, nullptr, nullptr, CCAT, 0, 0, nullptr, 0, 0, 0, nullptr, 1.f, CHID, 1);

    // 5) RoPE
    rope_k_kernel<<<(CB * CS * 64) / 256, 256>>>(ckv);
    rope_q_kernel<<<(CB * CS * CNH * 64) / 256, 256>>>(qsh, qsl, qch, qcl);

    // 6) q_lat -> qcat cols [0,512)  K=128, Z=32, split out
    mma_gemm<256><<<dim3(CKVLR / 256, CS / 128, CB * CNH), 256, SMEM256>>>(
        qsh, qsl, CNH * CQHD, LS * CNH * CQHD, CQHD,
        qabh, qabl, CHD, 0, (long long)CKVLR * CHD,
        nullptr, qch, qcl, CCAT, LS * CNH * CCAT, LS * CCAT,
        nullptr, 0, 0, 0, nullptr, 1.f, CHD, CNH);

    // 7) splits of ckv
    cvt_split_kernel<<<CVG, 256>>>(ckv, ckvh, ckvl, (long long)CBS * CCAT);
    cvt_ckvt_kernel<<<CVG, 256>>>(ckv, ckvth, ckvtl);

    // 8) scores = (qcat . ckv^T)*scale + mask  K=640, Z=32, fp32 out
    float scale = 1.f / sqrtf((float)CCAT);
    mma_gemm<256><<<dim3(CS / 256, CS / 128, CB * CNH), 256, SMEM256>>>(
        qch, qcl, CCAT, LS * CNH * CCAT, LS * CCAT,
        ckvh, ckvl, CCAT, LS * CCAT, 0,
        sc, nullptr, nullptr, CS, LS * CNH * CS, LS * CS,
        mask, CS, LS * CS, 0, nullptr, scale, CCAT, CNH);

    // 9) softmax -> split (single-read)
    softmax_split_kernel<<<CB * CNH * CS, 256>>>(sc, atth, attl);

    // 10) out_lat = attn @ ckv[:, :512]  K=2048, Z=32 (ckvT), split out
    mma_gemm<256><<<dim3(CKVLR / 256, CS / 128, CB * CNH), 256, SMEM256>>>(
        atth, attl, CS, LS * CNH * CS, LS * CS,
        ckvth, ckvtl, CS, (long long)CKVLR * CS, 0,
        nullptr, olh, oll, CKVLR, LS * CNH * CKVLR, LS * CKVLR,
        nullptr, 0, 0, 0, nullptr, 1.f, CS, CNH);

    // 11) out_head = olat . o_absorb^T -> [b,s,h*128+d]  K=512, N=128, Z=32, split out
    mma_gemm<128><<<dim3(1, CS / 128, CB * CNH), 256, SMEM128>>>(
        olh, oll, CKVLR, LS * CNH * CKVLR, LS * CKVLR,
        oabth, oabtl, CKVLR, 0, (long long)CHD * CKVLR,
        nullptr, ohh, ohl, CNH * CHD, LS * (long long)CNH * CHD, CHD,
        nullptr, 0, 0, 0, nullptr, 1.f, CKVLR, CNH);

    // 12) final = ohead @ o_W^T  [4096,2048] K=2048, fp32 out
    mma_gemm<256><<<dim3(CHID / 256, CBS / 128, 1), 256, SMEM256>>>(
        ohh, ohl, CNH * CHD, 0, 0, owh, owl, CNH * CHD, 0, 0,
        out, nullptr, nullptr, CHID, 0, 0, nullptr, 0, 0, 0, nullptr, 1.f, CNH * CHD, 1);
}

// round 6
// speedup vs baseline: 2.5694x; 1.0096x over previous
#include <cuda_runtime.h>
#include <cuda_bf16.h>
#include <math.h>
#include <stdint.h>

// ---------------- problem constants ----------------
#define CB   2
#define CS   2048
#define CHID 2048
#define CNH  16
#define CHD  128
#define CQLR 1536
#define CKVLR 512
#define CBS  (CB*CS)          // 4096
#define CCAT (CKVLR+CHD)      // 640
#define CQHD (2*CHD)          // 256

typedef __nv_bfloat16 bf16;

// ---------------- device scratch ----------------
static __device__ __align__(256) float g_qa[(size_t)CBS*CQLR];
static __device__ __align__(256) float g_ckv[(size_t)CBS*CCAT];

static __device__ __align__(256) bf16 g_hid_h[(size_t)CBS*CHID],  g_hid_l[(size_t)CBS*CHID];
static __device__ __align__(256) bf16 g_qaw_h[(size_t)CQLR*CHID], g_qaw_l[(size_t)CQLR*CHID];
static __device__ __align__(256) bf16 g_qbw_h[(size_t)CNH*CQHD*CQLR], g_qbw_l[(size_t)CNH*CQHD*CQLR];
static __device__ __align__(256) bf16 g_kvaw_h[(size_t)CCAT*CHID], g_kvaw_l[(size_t)CCAT*CHID];
static __device__ __align__(256) bf16 g_ow_h[(size_t)CHID*CNH*CHD], g_ow_l[(size_t)CHID*CNH*CHD];
static __device__ __align__(256) bf16 g_qan_h[(size_t)CBS*CQLR], g_qan_l[(size_t)CBS*CQLR];
static __device__ __align__(256) bf16 g_qs_h[(size_t)CBS*CNH*CQHD], g_qs_l[(size_t)CBS*CNH*CQHD];
static __device__ __align__(256) bf16 g_qab_h[(size_t)CNH*CKVLR*CHD], g_qab_l[(size_t)CNH*CKVLR*CHD];     // [h][c][d]
static __device__ __align__(256) bf16 g_oabt_h[(size_t)CNH*CHD*CKVLR], g_oabt_l[(size_t)CNH*CHD*CKVLR];   // [h][d][c]
static __device__ __align__(256) bf16 g_qc_h[(size_t)CB*CNH*CS*CCAT], g_qc_l[(size_t)CB*CNH*CS*CCAT];
static __device__ __align__(256) bf16 g_ckv_h[(size_t)CBS*CCAT], g_ckv_l[(size_t)CBS*CCAT];
static __device__ __align__(256) bf16 g_ol_h[(size_t)CB*CNH*CS*CKVLR], g_ol_l[(size_t)CB*CNH*CS*CKVLR];
static __device__ __align__(256) bf16 g_oh_h[(size_t)CBS*CNH*CHD], g_oh_l[(size_t)CBS*CNH*CHD];

// ---------------- asm helpers (sm_80-portable) ----------------
__device__ __forceinline__ uint32_t smem_u32(const void* p) {
    uint32_t a;
    asm("{ .reg .u64 t; cvta.to.shared.u64 t, %1; cvt.u32.u64 %0, t; }" : "=r"(a) : "l"(p));
    return a;
}
#define CP_ASYNC16(dst, src) \
    asm volatile("cp.async.cg.shared.global [%0], [%1], 16;" :: "r"(dst), "l"(src) : "memory")
#define CP_COMMIT() asm volatile("cp.async.commit_group;" ::: "memory")
#define CP_WAIT(n)  asm volatile("cp.async.wait_group %0;" :: "n"(n) : "memory")

#define LDSM4(r, addr) \
    asm volatile("ldmatrix.sync.aligned.m8n8.x4.shared.b16 {%0,%1,%2,%3}, [%4];" \
        : "=r"((r)[0]),"=r"((r)[1]),"=r"((r)[2]),"=r"((r)[3]) : "r"(addr))
#define LDSM4T(r, addr) \
    asm volatile("ldmatrix.sync.aligned.m8n8.x4.trans.shared.b16 {%0,%1,%2,%3}, [%4];" \
        : "=r"((r)[0]),"=r"((r)[1]),"=r"((r)[2]),"=r"((r)[3]) : "r"(addr))

#define MMA16816(d, a, b0, b1) \
    asm volatile("mma.sync.aligned.m16n8k16.row.col.f32.bf16.bf16.f32 " \
        "{%0,%1,%2,%3},{%4,%5,%6,%7},{%8,%9},{%0,%1,%2,%3};" \
        : "+f"((d)[0]),"+f"((d)[1]),"+f"((d)[2]),"+f"((d)[3]) \
        : "r"((a)[0]),"r"((a)[1]),"r"((a)[2]),"r"((a)[3]), "r"(b0),"r"(b1))

__device__ __forceinline__ void split2(float v, bf16* hp, bf16* lp) {
    bf16 h = __float2bfloat16(v);
    *hp = h;
    *lp = __float2bfloat16(v - __bfloat162float(h));
}
__device__ __forceinline__ void split2x2(float v0, float v1, bf16* hp, bf16* lp) {
    bf16 h0 = __float2bfloat16(v0), h1 = __float2bfloat16(v1);
    bf16 l0 = __float2bfloat16(v0 - __bfloat162float(h0));
    bf16 l1 = __float2bfloat16(v1 - __bfloat162float(h1));
    __nv_bfloat162 hh; hh.x = h0; hh.y = h1;
    __nv_bfloat162 ll; ll.x = l0; ll.y = l1;
    *reinterpret_cast<__nv_bfloat162*>(hp) = hh;
    *reinterpret_cast<__nv_bfloat162*>(lp) = ll;
}

// ---------------- bf16 hi/lo split MMA GEMM (unchanged from R5) ----------------
static constexpr int GBK = 32, STAGES = 4;
static constexpr int ASZ = 128 * GBK * 2;   // 8192 B

__device__ __forceinline__ uint32_t swz(int row, int ch) {
    return (uint32_t)(row * 64 + ((ch ^ ((row >> 1) & 3)) * 16));
}

template<int BN>
__global__ __launch_bounds__(256, 1) void mma_gemm(
    const bf16* __restrict__ Ah, const bf16* __restrict__ Al, int lda, long long aO, long long aI,
    const bf16* __restrict__ Bh, const bf16* __restrict__ Bl, int ldb, long long bO, long long bI,
    float* __restrict__ C, bf16* __restrict__ Chi, bf16* __restrict__ Clo,
    int ldc, long long cO, long long cI,
    const float* __restrict__ bias, float alpha, int K, int zInner)
{
    constexpr int TM = (BN == 256) ? 4 : 2;
    constexpr int BSZ = BN * GBK * 2;
    constexpr int BCH = BN * 4;
    constexpr int STAGE_B = 2 * ASZ + 2 * BSZ;

    extern __shared__ char smem_raw[];
    uint32_t sbase = smem_u32(smem_raw);

    int tid = threadIdx.x, wid = tid >> 5, lane = tid & 31;
    int z = blockIdx.z, zo = z / zInner, zi = z - zo * zInner;
    Ah += zo * aO + zi * aI;  Al += zo * aO + zi * aI;
    Bh += zo * bO + zi * bI;  Bl += zo * bO + zi * bI;
    if (C)   C   += zo * cO + zi * cI;
    if (Chi) { Chi += zo * cO + zi * cI; Clo += zo * cO + zi * cI; }

    int bm = blockIdx.y * 128, bn = blockIdx.x * BN;
    int wm, wn;
    if (BN == 256) { wm = (wid & 1) * 64; wn = (wid >> 1) * 64; }
    else           { wm = (wid & 3) * 32; wn = (wid >> 2) * 64; }

    const bf16* pAh = Ah + (long long)bm * lda;
    const bf16* pAl = Al + (long long)bm * lda;
    const bf16* pBh = Bh + (long long)bn * ldb;
    const bf16* pBl = Bl + (long long)bn * ldb;

    float acc[TM][8][4];
#pragma unroll
    for (int t = 0; t < TM; t++)
#pragma unroll
        for (int j = 0; j < 8; j++)
#pragma unroll
            for (int q = 0; q < 4; q++) acc[t][j][q] = 0.f;

    int nk = K / GBK;

#define ISSUE(stage_) do { \
    int st_ = (stage_) % STAGES; \
    uint32_t sb_ = sbase + st_ * STAGE_B; \
    long long k0_ = (long long)(stage_) * GBK; \
    _Pragma("unroll") \
    for (int u = 0; u < 2; u++) { \
        int idx = u * 256 + tid; int r = idx >> 2, ch = idx & 3; \
        uint32_t so = swz(r, ch); \
        CP_ASYNC16(sb_ + so,       pAh + (long long)r * lda + k0_ + ch * 8); \
        CP_ASYNC16(sb_ + ASZ + so, pAl + (long long)r * lda + k0_ + ch * 8); \
    } \
    _Pragma("unroll") \
    for (int u = 0; u < BCH / 256; u++) { \
        int idx = u * 256 + tid; int r = idx >> 2, ch = idx & 3; \
        uint32_t so = swz(r, ch); \
        CP_ASYNC16(sb_ + 2 * ASZ + so,       pBh + (long long)r * ldb + k0_ + ch * 8); \
        CP_ASYNC16(sb_ + 2 * ASZ + BSZ + so, pBl + (long long)r * ldb + k0_ + ch * 8); \
    } \
} while (0)

    for (int s = 0; s < STAGES - 1; s++) {
        if (s < nk) ISSUE(s);
        CP_COMMIT();
    }

    int a_row = (lane & 15);
    int a_sel = lane >> 4;
    int b_g   = lane >> 3;
    int b_row = (lane & 7) + ((b_g >> 1) * 8);
    int b_sel = b_g & 1;

    for (int i = 0; i < nk; i++) {
        CP_WAIT(STAGES - 2);
        __syncthreads();
        if (i + STAGES - 1 < nk) ISSUE(i + STAGES - 1);
        CP_COMMIT();

        uint32_t sb = sbase + (i % STAGES) * STAGE_B;

#pragma unroll
        for (int kh = 0; kh < 2; kh++) {
            uint32_t Afh[TM][4], Afl[TM][4];
#pragma unroll
            for (int t = 0; t < TM; t++) {
                int row = wm + t * 16 + a_row;
                int ck = 2 * kh + a_sel;
                uint32_t off = swz(row, ck);
                LDSM4(Afh[t], sb + off);
                LDSM4(Afl[t], sb + ASZ + off);
            }
            uint32_t Bfh[4][4], Bfl[4][4];
#pragma unroll
            for (int j = 0; j < 4; j++) {
                int row = wn + j * 16 + b_row;
                int ck = 2 * kh + b_sel;
                uint32_t off = swz(row, ck);
                LDSM4(Bfh[j], sb + 2 * ASZ + off);
                LDSM4(Bfl[j], sb + 2 * ASZ + BSZ + off);
            }
#pragma unroll
            for (int t = 0; t < TM; t++)
#pragma unroll
                for (int j = 0; j < 4; j++) {
                    MMA16816(acc[t][2*j],   Afh[t], Bfh[j][0], Bfh[j][1]);
                    MMA16816(acc[t][2*j],   Afh[t], Bfl[j][0], Bfl[j][1]);
                    MMA16816(acc[t][2*j],   Afl[t], Bfh[j][0], Bfh[j][1]);
                    MMA16816(acc[t][2*j+1], Afh[t], Bfh[j][2], Bfh[j][3]);
                    MMA16816(acc[t][2*j+1], Afh[t], Bfl[j][2], Bfl[j][3]);
                    MMA16816(acc[t][2*j+1], Afl[t], Bfh[j][2], Bfh[j][3]);
                }
        }
    }
#undef ISSUE

#pragma unroll
    for (int t = 0; t < TM; t++) {
        int r0 = bm + wm + t * 16 + (lane >> 2);
#pragma unroll
        for (int j = 0; j < 8; j++) {
            int col = bn + wn + j * 8 + (lane & 3) * 2;
            float v0 = acc[t][j][0] * alpha;
            float v1 = acc[t][j][1] * alpha;
            float v2 = acc[t][j][2] * alpha;
            float v3 = acc[t][j][3] * alpha;
            if (bias) { v0 += bias[col]; v1 += bias[col + 1]; v2 += bias[col]; v3 += bias[col + 1]; }
            if (Chi) {
                long long o0 = (long long)r0 * ldc + col;
                long long o1 = (long long)(r0 + 8) * ldc + col;
                split2x2(v0, v1, Chi + o0, Clo + o0);
                split2x2(v2, v3, Chi + o1, Clo + o1);
            } else {
                C[(long long)r0 * ldc + col]           = v0;
                C[(long long)r0 * ldc + col + 1]       = v1;
                C[(long long)(r0 + 8) * ldc + col]     = v2;
                C[(long long)(r0 + 8) * ldc + col + 1] = v3;
            }
        }
    }
}

// ---------------- fused flash attention ----------------
// CTA: 64 q rows, one (b,h). K' tile (64 keys x 640, hi/lo) resident in smem;
// V = K'[:, :512] read in-place via ldmatrix.trans. Max-free softmax.
// smem: K chunks 10 x (8K hi + 8K lo) = 160KB @0; Q ring 4 x 16KB @163840 (P overlays stage 0).
static constexpr int FQOFF = 163840;
static constexpr int FSMEM = 163840 + 4 * 16384;   // 224 KB

__device__ __forceinline__ uint32_t psw(int row, int ch) {
    return (uint32_t)(row * 128 + ((ch ^ (row & 7)) << 4));
}

__device__ __forceinline__ void fissue(uint32_t sbase, int kc,
    const bf16* pQh, const bf16* pQl, const bf16* pKhj, const bf16* pKlj,
    uint32_t soff0, uint32_t soff1, long long goff0, long long goff1)
{
    uint32_t kb = sbase + kc * 16384;
    uint32_t qb = sbase + FQOFF + (kc & 3) * 16384;
    long long co = (long long)kc * 64;
    CP_ASYNC16(kb + soff0,        pKhj + goff0 + co);
    CP_ASYNC16(kb + 8192 + soff0, pKlj + goff0 + co);
    CP_ASYNC16(qb + soff0,        pQh + goff0 + co);
    CP_ASYNC16(qb + 8192 + soff0, pQl + goff0 + co);
    CP_ASYNC16(kb + soff1,        pKhj + goff1 + co);
    CP_ASYNC16(kb + 8192 + soff1, pKlj + goff1 + co);
    CP_ASYNC16(qb + soff1,        pQh + goff1 + co);
    CP_ASYNC16(qb + 8192 + soff1, pQl + goff1 + co);
}

__global__ __launch_bounds__(256, 1) void flash_kernel(
    const bf16* __restrict__ Qh, const bf16* __restrict__ Ql,
    const bf16* __restrict__ Kh, const bf16* __restrict__ Kl,
    const float* __restrict__ mask,
    bf16* __restrict__ Oh, bf16* __restrict__ Ol,
    float scale)
{
    extern __shared__ char smem[];
    uint32_t sbase = smem_u32(smem);
    int tid = threadIdx.x, wid = tid >> 5, lane = tid & 31;
    int mg = wid & 3, cg = wid >> 2;
    int bh = blockIdx.y, b = bh >> 4;
    int q0 = blockIdx.x * 64;

    const bf16* pQh = Qh + (long long)bh * CS * CCAT + (long long)q0 * CCAT;
    const bf16* pQl = Ql + (long long)bh * CS * CCAT + (long long)q0 * CCAT;
    const bf16* pKh = Kh + (long long)b * CS * CCAT;
    const bf16* pKl = Kl + (long long)b * CS * CCAT;

    // cp.async geometry: 512 granules per 8KB chunk, 2 per thread
    int lrow0 = tid >> 3, lch = tid & 7;
    int lrow1 = lrow0 + 32;
    uint32_t soff0 = psw(lrow0, lch);
    uint32_t soff1 = psw(lrow1, lch);
    long long goff0 = (long long)lrow0 * CCAT + lch * 8;
    long long goff1 = (long long)lrow1 * CCAT + lch * 8;

    // ldmatrix lane geometry
    int arow = mg * 16 + (lane & 15);
    int asel = lane >> 4;
    int brow0 = cg * 32 + (lane & 7) + ((lane >> 4) * 8);
    int brow1 = brow0 + 16;
    int bsel = (lane >> 3) & 1;
    int trow_b = (lane & 7) + (((lane >> 3) & 1) * 8);   // + kt*16
    int tsel = lane >> 4;

    float oacc[32][4];
#pragma unroll
    for (int i = 0; i < 32; i++)
#pragma unroll
        for (int q = 0; q < 4; q++) oacc[i][q] = 0.f;
    float lsum0 = 0.f, lsum1 = 0.f;

    int prow0 = mg * 16 + (lane >> 2), prow1 = prow0 + 8;

    for (int j = 0; j < 32; j++) {
        const bf16* pKhj = pKh + (long long)j * 64 * CCAT;
        const bf16* pKlj = pKl + (long long)j * 64 * CCAT;

        fissue(sbase, 0, pQh, pQl, pKhj, pKlj, soff0, soff1, goff0, goff1); CP_COMMIT();
        fissue(sbase, 1, pQh, pQl, pKhj, pKlj, soff0, soff1, goff0, goff1); CP_COMMIT();

        float sacc[4][4];
#pragma unroll
        for (int n = 0; n < 4; n++)
#pragma unroll
            for (int q = 0; q < 4; q++) sacc[n][q] = 0.f;

        for (int kc = 0; kc < 10; kc++) {
            if (kc + 2 < 10) fissue(sbase, kc + 2, pQh, pQl, pKhj, pKlj, soff0, soff1, goff0, goff1);
            CP_COMMIT();
            CP_WAIT(2);
            __syncthreads();
            uint32_t kb = sbase + kc * 16384;
            uint32_t qb = sbase + FQOFF + (kc & 3) * 16384;
#pragma unroll
            for (int kk = 0; kk < 4; kk++) {
                uint32_t ao = psw(arow, kk * 2 + asel);
                uint32_t Ah4[4], Al4[4];
                LDSM4(Ah4, qb + ao);
                LDSM4(Al4, qb + 8192 + ao);
                uint32_t bo0 = psw(brow0, kk * 2 + bsel);
                uint32_t bo1 = psw(brow1, kk * 2 + bsel);
                uint32_t B0h[4], B1h[4], B0l[4], B1l[4];
                LDSM4(B0h, kb + bo0); LDSM4(B0l, kb + 8192 + bo0);
                LDSM4(B1h, kb + bo1); LDSM4(B1l, kb + 8192 + bo1);
                MMA16816(sacc[0], Ah4, B0h[0], B0h[1]);
                MMA16816(sacc[0], Ah4, B0l[0], B0l[1]);
                MMA16816(sacc[0], Al4, B0h[0], B0h[1]);
                MMA16816(sacc[1], Ah4, B0h[2], B0h[3]);
                MMA16816(sacc[1], Ah4, B0l[2], B0l[3]);
                MMA16816(sacc[1], Al4, B0h[2], B0h[3]);
                MMA16816(sacc[2], Ah4, B1h[0], B1h[1]);
                MMA16816(sacc[2], Ah4, B1l[0], B1l[1]);
                MMA16816(sacc[2], Al4, B1h[0], B1h[1]);
                MMA16816(sacc[3], Ah4, B1h[2], B1h[3]);
                MMA16816(sacc[3], Ah4, B1l[2], B1l[3]);
                MMA16816(sacc[3], Al4, B1h[2], B1h[3]);
            }
        }
        __syncthreads();   // all S-phase smem reads done (P overlays Q stage 0)

        // softmax (max-free) + P split write
        {
            const float* mrow = mask + (long long)b * CS * CS
                              + (long long)(q0 + prow0) * CS + j * 64 + cg * 32 + (lane & 3) * 2;
            float ladd0 = 0.f, ladd1 = 0.f;
#pragma unroll
            for (int nn = 0; nn < 4; nn++) {
                float2 m0 = *reinterpret_cast<const float2*>(mrow + nn * 8);
                float2 m1 = *reinterpret_cast<const float2*>(mrow + nn * 8 + 8 * CS);
                float p0 = __expf(sacc[nn][0] * scale + m0.x);
                float p1 = __expf(sacc[nn][1] * scale + m0.y);
                float p2 = __expf(sacc[nn][2] * scale + m1.x);
                float p3 = __expf(sacc[nn][3] * scale + m1.y);
                ladd0 += p0 + p1; ladd1 += p2 + p3;
                int col = cg * 32 + nn * 8 + (lane & 3) * 2;
                uint32_t o0 = (uint32_t)(prow0 * 128 + ((((col >> 3)) ^ (prow0 & 7)) << 4) + (col & 7) * 2);
                uint32_t o1 = (uint32_t)(prow1 * 128 + ((((col >> 3)) ^ (prow1 & 7)) << 4) + (col & 7) * 2);
                split2x2(p0, p1, (bf16*)(smem + FQOFF + o0), (bf16*)(smem + FQOFF + 8192 + o0));
                split2x2(p2, p3, (bf16*)(smem + FQOFF + o1), (bf16*)(smem + FQOFF + 8192 + o1));
            }
            ladd0 += __shfl_xor_sync(~0u, ladd0, 1); ladd0 += __shfl_xor_sync(~0u, ladd0, 2);
            ladd1 += __shfl_xor_sync(~0u, ladd1, 1); ladd1 += __shfl_xor_sync(~0u, ladd1, 2);
            lsum0 += ladd0; lsum1 += ladd1;
        }
        __syncthreads();   // P visible to all warps

        // AV: O += P * V, V = K chunks 0..7 via ldmatrix.trans
#pragma unroll
        for (int kt = 0; kt < 4; kt++) {
            uint32_t ao = psw(arow, kt * 2 + asel);
            uint32_t Ph4[4], Pl4[4];
            LDSM4(Ph4, sbase + FQOFF + ao);
            LDSM4(Pl4, sbase + FQOFF + 8192 + ao);
            int trow = kt * 16 + trow_b;
#pragma unroll
            for (int ng = 0; ng < 16; ng++) {
                int c0 = cg * 256 + ng * 16;
                uint32_t kcb = sbase + (c0 >> 6) * 16384;
                uint32_t bo = psw(trow, ((c0 & 63) >> 3) + tsel);
                uint32_t Vh4[4], Vl4[4];
                LDSM4T(Vh4, kcb + bo);
                LDSM4T(Vl4, kcb + 8192 + bo);
                MMA16816(oacc[ng*2],   Ph4, Vh4[0], Vh4[1]);
                MMA16816(oacc[ng*2],   Ph4, Vl4[0], Vl4[1]);
                MMA16816(oacc[ng*2],   Pl4, Vh4[0], Vh4[1]);
                MMA16816(oacc[ng*2+1], Ph4, Vh4[2], Vh4[3]);
                MMA16816(oacc[ng*2+1], Ph4, Vl4[2], Vl4[3]);
                MMA16816(oacc[ng*2+1], Pl4, Vh4[2], Vh4[3]);
            }
        }
        __syncthreads();   // AV reads done before next j overwrites K/Q/P
    }

    // finalize: combine row sums across cg halves, normalize, split-write O
    float* Larr = reinterpret_cast<float*>(smem);
    if ((lane & 3) == 0) {
        Larr[cg * 64 + prow0] = lsum0;
        Larr[cg * 64 + prow1] = lsum1;
    }
    __syncthreads();
    float inv0 = 1.f / (Larr[prow0] + Larr[64 + prow0]);
    float inv1 = 1.f / (Larr[prow1] + Larr[64 + prow1]);

    bf16* poh = Oh + (long long)bh * CS * CKVLR + (long long)q0 * CKVLR;
    bf16* pol = Ol + (long long)bh * CS * CKVLR + (long long)q0 * CKVLR;
#pragma unroll
    for (int ng = 0; ng < 16; ng++) {
#pragma unroll
        for (int h8 = 0; h8 < 2; h8++) {
            int c = cg * 256 + ng * 16 + h8 * 8 + (lane & 3) * 2;
            float* a = oacc[ng * 2 + h8];
            long long o0 = (long long)prow0 * CKVLR + c;
            long long o1 = (long long)prow1 * CKVLR + c;
            split2x2(a[0] * inv0, a[1] * inv0, poh + o0, pol + o0);
            split2x2(a[2] * inv1, a[3] * inv1, poh + o1, pol + o1);
        }
    }
}

// ---------------- conversions ----------------
__global__ void cvt_split_kernel(const float* __restrict__ s, bf16* __restrict__ hi, bf16* __restrict__ lo, long long n)
{
    long long i = (long long)blockIdx.x * blockDim.x + threadIdx.x;
    long long st = (long long)gridDim.x * blockDim.x;
    for (; i < n; i += st) split2(s[i], hi + i, lo + i);
}

__global__ void extract_kernel(const float* __restrict__ kvb,
                               bf16* __restrict__ qh, bf16* __restrict__ ql,
                               bf16* __restrict__ oh, bf16* __restrict__ ol)
{
    long long n = (long long)CNH * CKVLR * CHD;
    long long i = (long long)blockIdx.x * blockDim.x + threadIdx.x;
    long long st = (long long)gridDim.x * blockDim.x;
    for (; i < n; i += st) {
        {
            int c = (int)(i & 511);
            int d = (int)((i >> 9) & 127);
            int h = (int)(i >> 16);
            float v = kvb[(((long long)c * CNH + h) * 2 + 1) * CHD + d];
            split2(v, oh + i, ol + i);
        }
        {
            int d = (int)(i & 127);
            int c = (int)((i >> 7) & 511);
            int h = (int)(i >> 16);
            float v = kvb[(((long long)c * CNH + h) * 2) * CHD + d];
            split2(v, qh + i, ql + i);
        }
    }
}

// ---------------- RMSNorm ----------------
__global__ __launch_bounds__(256) void rms_kernel(const float* __restrict__ x, const float* __restrict__ w,
                                                  bf16* __restrict__ hi, bf16* __restrict__ lo)
{
    __shared__ float red[8];
    size_t row = blockIdx.x;
    const float* p = x + row * CQLR;
    int tid = threadIdx.x;
    float s = 0.f;
    for (int i = tid; i < CQLR; i += 256) { float v = p[i]; s += v * v; }
#pragma unroll
    for (int o = 16; o; o >>= 1) s += __shfl_xor_sync(~0u, s, o);
    if ((tid & 31) == 0) red[tid >> 5] = s;
    __syncthreads();
    float tot = 0.f;
#pragma unroll
    for (int i = 0; i < 8; i++) tot += red[i];
    float r = rsqrtf(tot + 1e-6f);
    bf16* ph = hi + row * CQLR;
    bf16* pl = lo + row * CQLR;
    for (int i = tid; i < CQLR; i += 256) split2(p[i] * r * w[i], ph + i, pl + i);
}

// ---------------- RoPE ----------------
__device__ __forceinline__ void rope_cs(int s, int i, float& c, float& sn)
{
    double invf = pow(10000.0, -(double)(2 * i) / 128.0);
    double ang = (double)s * invf;
    c = (float)cos(ang);
    sn = (float)sin(ang);
}

__global__ void rope_k_kernel(float* __restrict__ ckv)
{
    int idx = blockIdx.x * blockDim.x + threadIdx.x;
    if (idx >= CB * CS * 64) return;
    int i = idx & 63;
    int row = idx >> 6;
    int s = row & (CS - 1);
    float c, sn; rope_cs(s, i, c, sn);
    float* p = ckv + (size_t)row * CCAT + CKVLR;
    float x1 = p[i], x2 = p[i + 64];
    p[i]      = x1 * c - x2 * sn;
    p[i + 64] = x2 * c + x1 * sn;
}

__global__ void rope_q_kernel(const bf16* __restrict__ qh, const bf16* __restrict__ ql,
                              bf16* __restrict__ qch, bf16* __restrict__ qcl)
{
    int idx = blockIdx.x * blockDim.x + threadIdx.x;
    if (idx >= CB * CS * CNH * 64) return;
    int i = idx & 63;
    int h = (idx >> 6) & 15;
    int row = idx >> 10;
    int s = row & (CS - 1);
    int b = row >> 11;
    float c, sn; rope_cs(s, i, c, sn);
    long long so = (long long)row * (CNH * CQHD) + h * CQHD + CHD;
    float x1 = __bfloat162float(qh[so + i])      + __bfloat162float(ql[so + i]);
    float x2 = __bfloat162float(qh[so + i + 64]) + __bfloat162float(ql[so + i + 64]);
    long long dofs = ((long long)(b * CNH + h) * CS + s) * CCAT + CKVLR;
    split2(x1 * c - x2 * sn, qch + dofs + i,      qcl + dofs + i);
    split2(x2 * c + x1 * sn, qch + dofs + i + 64, qcl + dofs + i + 64);
}

// ---------------- launch ----------------
extern "C" void kernel_launch(void* const* d_in, const int* in_sizes, int n_in,
                              void* d_out, int out_size)
{
    const float* hidden = (const float*)d_in[0];
    const float* mask   = (const float*)d_in[1];
    const float* q_a_W  = (const float*)d_in[2];
    const float* q_a_b  = (const float*)d_in[3];
    const float* q_a_nw = (const float*)d_in[4];
    const float* q_b_W  = (const float*)d_in[5];
    const float* kv_a_W = (const float*)d_in[6];
    const float* kv_b_W = (const float*)d_in[7];
    const float* o_W    = (const float*)d_in[8];
    float* out = (float*)d_out;

    void* p;
#define SYM(v, g) cudaGetSymbolAddress(&p, g); auto* v = (decltype(&g[0]))p
    SYM(qa, g_qa);     SYM(ckv, g_ckv);
    SYM(hidh, g_hid_h); SYM(hidl, g_hid_l);
    SYM(qawh, g_qaw_h); SYM(qawl, g_qaw_l);
    SYM(qbwh, g_qbw_h); SYM(qbwl, g_qbw_l);
    SYM(kvawh, g_kvaw_h); SYM(kvawl, g_kvaw_l);
    SYM(owh, g_ow_h);   SYM(owl, g_ow_l);
    SYM(qanh, g_qan_h); SYM(qanl, g_qan_l);
    SYM(qsh, g_qs_h);   SYM(qsl, g_qs_l);
    SYM(qabh, g_qab_h); SYM(qabl, g_qab_l);
    SYM(oabth, g_oabt_h); SYM(oabtl, g_oabt_l);
    SYM(qch, g_qc_h);   SYM(qcl, g_qc_l);
    SYM(ckvh, g_ckv_h); SYM(ckvl, g_ckv_l);
    SYM(olh, g_ol_h);   SYM(oll, g_ol_l);
    SYM(ohh, g_oh_h);   SYM(ohl, g_oh_l);
#undef SYM

    constexpr int SMEM128 = STAGES * (2 * ASZ + 2 * 128 * GBK * 2);  // 128 KB
    constexpr int SMEM256 = STAGES * (2 * ASZ + 2 * 256 * GBK * 2);  // 192 KB
    cudaFuncSetAttribute(mma_gemm<128>, cudaFuncAttributeMaxDynamicSharedMemorySize, SMEM128);
    cudaFuncSetAttribute(mma_gemm<256>, cudaFuncAttributeMaxDynamicSharedMemorySize, SMEM256);
    cudaFuncSetAttribute(flash_kernel, cudaFuncAttributeMaxDynamicSharedMemorySize, FSMEM);

    const long long LS = CS;
    const int CVG = 2048;

    cvt_split_kernel<<<CVG, 256>>>(hidden, hidh, hidl, (long long)CBS * CHID);
    cvt_split_kernel<<<CVG, 256>>>(q_a_W, qawh, qawl, (long long)CQLR * CHID);
    cvt_split_kernel<<<CVG, 256>>>(q_b_W, qbwh, qbwl, (long long)CNH * CQHD * CQLR);
    cvt_split_kernel<<<CVG, 256>>>(o_W, owh, owl, (long long)CHID * CNH * CHD);
    cvt_split_kernel<<<CVG, 256>>>(kv_a_W, kvawh, kvawl, (long long)CCAT * CHID);
    extract_kernel<<<CVG, 256>>>(kv_b_W, qabh, qabl, oabth, oabtl);

    // 1) q_a = hidden @ q_a_W^T + bias   [4096,1536] K=2048, fp32 out
    mma_gemm<256><<<dim3(CQLR / 256, CBS / 128, 1), 256, SMEM256>>>(
        hidh, hidl, CHID, 0, 0, qawh, qawl, CHID, 0, 0,
        qa, nullptr, nullptr, CQLR, 0, 0, q_a_b, 1.f, CHID, 1);

    // 2) rmsnorm -> split
    rms_kernel<<<CBS, 256>>>(qa, q_a_nw, qanh, qanl);

    // 3) q = qa_norm @ q_b_W^T  [4096,4096] K=1536, split out
    mma_gemm<256><<<dim3((CNH * CQHD) / 256, CBS / 128, 1), 256, SMEM256>>>(
        qanh, qanl, CQLR, 0, 0, qbwh, qbwl, CQLR, 0, 0,
        nullptr, qsh, qsl, CNH * CQHD, 0, 0, nullptr, 1.f, CQLR, 1);

    // 4) ckv = hidden @ kv_a_W^T  [4096,640] K=2048, fp32 out
    mma_gemm<128><<<dim3(CCAT / 128, CBS / 128, 1), 256, SMEM128>>>(
        hidh, hidl, CHID, 0, 0, kvawh, kvawl, CHID, 0, 0,
        ckv, nullptr, nullptr, CCAT, 0, 0, nullptr, 1.f, CHID, 1);

    // 5) RoPE
    rope_k_kernel<<<(CB * CS * 64) / 256, 256>>>(ckv);
    rope_q_kernel<<<(CB * CS * CNH * 64) / 256, 256>>>(qsh, qsl, qch, qcl);

    // 6) q_lat -> qcat cols [0,512)  K=128, Z=32, split out
    mma_gemm<256><<<dim3(CKVLR / 256, CS / 128, CB * CNH), 256, SMEM256>>>(
        qsh, qsl, CNH * CQHD, LS * CNH * CQHD, CQHD,
        qabh, qabl, CHD, 0, (long long)CKVLR * CHD,
        nullptr, qch, qcl, CCAT, LS * CNH * CCAT, LS * CCAT,
        nullptr, 1.f, CHD, CNH);

    // 7) split ckv (K-major)
    cvt_split_kernel<<<CVG, 256>>>(ckv, ckvh, ckvl, (long long)CBS * CCAT);

    // 8) fused attention: scores + softmax + AV -> olat split
    float scale = 1.f / sqrtf((float)CCAT);
    flash_kernel<<<dim3(CS / 64, CB * CNH), 256, FSMEM>>>(
        qch, qcl, ckvh, ckvl, mask, olh, oll, scale);

    // 9) out_head = olat . o_absorb^T -> [b,s,h*128+d]  K=512, N=128, Z=32, split out
    mma_gemm<128><<<dim3(1, CS / 128, CB * CNH), 256, SMEM128>>>(
        olh, oll, CKVLR, LS * CNH * CKVLR, LS * CKVLR,
        oabth, oabtl, CKVLR, 0, (long long)CHD * CKVLR,
        nullptr, ohh, ohl, CNH * CHD, LS * (long long)CNH * CHD, CHD,
        nullptr, 1.f, CKVLR, CNH);

    // 10) final = ohead @ o_W^T  [4096,2048] K=2048, fp32 out
    mma_gemm<256><<<dim3(CHID / 256, CBS / 128, 1), 256, SMEM256>>>(
        ohh, ohl, CNH * CHD, 0, 0, owh, owl, CNH * CHD, 0, 0,
        out, nullptr, nullptr, CHID, 0, 0, nullptr, 1.f, CNH * CHD, 1);
}